// round 12
// baseline (speedup 1.0000x reference)
#include <cuda_runtime.h>
#include <cuda_bf16.h>
#include <cstdint>
#include <math.h>

#define D_MODEL 1024
#define NH      16
#define DH      64
#define BATCH   2
#define T       2048
#define BT      4096
#define QKV_N   3072

typedef __nv_bfloat16 bf16;
typedef __nv_bfloat162 bf162;

// ---------------------------------------------------------------------------
// Scratch
// ---------------------------------------------------------------------------
__device__ bf16 g_h_hi[(size_t)BT * D_MODEL];
__device__ bf16 g_h_lo[(size_t)BT * D_MODEL];
__device__ bf16 g_wq_hi[(size_t)QKV_N * D_MODEL];
__device__ bf16 g_wq_lo[(size_t)QKV_N * D_MODEL];
__device__ bf16 g_wo_hi[(size_t)D_MODEL * D_MODEL];
__device__ bf16 g_wo_lo[(size_t)D_MODEL * D_MODEL];
__device__ bf16 g_q_hi[(size_t)32 * T * DH];
__device__ bf16 g_q_lo[(size_t)32 * T * DH];
__device__ bf16 g_k_hi[(size_t)32 * T * DH];
__device__ bf16 g_k_lo[(size_t)32 * T * DH];
__device__ bf16 g_v_hi[(size_t)32 * T * DH];
__device__ bf16 g_v_lo[(size_t)32 * T * DH];
__device__ bf16 g_ao_hi[(size_t)BT * D_MODEL];
__device__ bf16 g_ao_lo[(size_t)BT * D_MODEL];
__device__ float2 g_part[(size_t)32 * T * 16];
__device__ float  g_m[(size_t)32 * T];
__device__ float  g_inv[(size_t)32 * T];

// ---------------------------------------------------------------------------
// Helpers
// ---------------------------------------------------------------------------
__device__ __forceinline__ uint32_t smem_u32(const void* p) {
    uint32_t a;
    asm("{ .reg .u64 t; cvta.to.shared.u64 t, %1; cvt.u32.u64 %0, t; }" : "=r"(a) : "l"(p));
    return a;
}
__device__ __forceinline__ void cp16(uint32_t dst, const void* src) {
    asm volatile("cp.async.cg.shared.global [%0], [%1], 16;" :: "r"(dst), "l"(src));
}
#define CP_COMMIT() asm volatile("cp.async.commit_group;" ::: "memory")
#define CP_WAIT0()  asm volatile("cp.async.wait_group 0;" ::: "memory")
#define CP_WAIT1()  asm volatile("cp.async.wait_group 1;" ::: "memory")
#define LDSM4(r0, r1, r2, r3, addr)                                              \
    asm volatile("ldmatrix.sync.aligned.m8n8.x4.shared.b16 {%0,%1,%2,%3}, [%4];" \
                 : "=r"(r0), "=r"(r1), "=r"(r2), "=r"(r3) : "r"(addr))
#define LDSM4T(r0, r1, r2, r3, addr)                                                   \
    asm volatile("ldmatrix.sync.aligned.m8n8.x4.trans.shared.b16 {%0,%1,%2,%3}, [%4];" \
                 : "=r"(r0), "=r"(r1), "=r"(r2), "=r"(r3) : "r"(addr))
#define MMA16816(c, a, b0, b1)                                                   \
    asm volatile("mma.sync.aligned.m16n8k16.row.col.f32.bf16.bf16.f32 "          \
                 "{%0,%1,%2,%3}, {%4,%5,%6,%7}, {%8,%9}, {%0,%1,%2,%3};"         \
                 : "+f"((c)[0]), "+f"((c)[1]), "+f"((c)[2]), "+f"((c)[3])        \
                 : "r"((a)[0]), "r"((a)[1]), "r"((a)[2]), "r"((a)[3]),           \
                   "r"(b0), "r"(b1))

__device__ __forceinline__ void ms_merge(float& m, float& s, float om, float os) {
    float M = fmaxf(m, om);
    s = s * __expf(m - M) + os * __expf(om - M);
    m = M;
}
__device__ __forceinline__ uint32_t packbf(float a, float b) {
    bf162 v; v.x = __float2bfloat16(a); v.y = __float2bfloat16(b);
    return *(uint32_t*)&v;
}

// ---------------------------------------------------------------------------
// LayerNorm -> bf16 hi/lo split
// ---------------------------------------------------------------------------
__global__ void ln_kernel(const float* __restrict__ x, const float* __restrict__ gam,
                          const float* __restrict__ bet,
                          bf16* __restrict__ ohi, bf16* __restrict__ olo) {
    int row = blockIdx.x;
    const float* xr = x + (size_t)row * D_MODEL;
    float v[4];
    float s = 0.f, s2 = 0.f;
#pragma unroll
    for (int i = 0; i < 4; i++) {
        v[i] = xr[threadIdx.x + i * 256];
        s += v[i]; s2 += v[i] * v[i];
    }
#pragma unroll
    for (int o = 16; o > 0; o >>= 1) {
        s  += __shfl_xor_sync(~0u, s, o);
        s2 += __shfl_xor_sync(~0u, s2, o);
    }
    __shared__ float rs[8], rs2[8];
    int wid = threadIdx.x >> 5, lid = threadIdx.x & 31;
    if (lid == 0) { rs[wid] = s; rs2[wid] = s2; }
    __syncthreads();
    s = 0.f; s2 = 0.f;
#pragma unroll
    for (int i = 0; i < 8; i++) { s += rs[i]; s2 += rs2[i]; }
    float mu  = s * (1.f / D_MODEL);
    float var = s2 * (1.f / D_MODEL) - mu * mu;
    float inv = rsqrtf(var + 1e-5f);
#pragma unroll
    for (int i = 0; i < 4; i++) {
        int c = threadIdx.x + i * 256;
        float y = (v[i] - mu) * inv * gam[c] + bet[c];
        bf16 h = __float2bfloat16(y);
        ohi[(size_t)row * D_MODEL + c] = h;
        olo[(size_t)row * D_MODEL + c] = __float2bfloat16(y - __bfloat162float(h));
    }
}

// ---------------------------------------------------------------------------
// Transpose + bf16 split: W[K][N] -> out[N][K]
// ---------------------------------------------------------------------------
__global__ void tsplit_kernel(const float* __restrict__ W,
                              bf16* __restrict__ hi, bf16* __restrict__ lo,
                              int K, int N) {
    __shared__ float t[32][33];
    int n0 = blockIdx.x * 32, k0 = blockIdx.y * 32;
    int tx = threadIdx.x, ty = threadIdx.y;
#pragma unroll
    for (int j = 0; j < 4; j++)
        t[ty + j * 8][tx] = W[(size_t)(k0 + ty + j * 8) * N + n0 + tx];
    __syncthreads();
#pragma unroll
    for (int j = 0; j < 4; j++) {
        float v = t[tx][ty + j * 8];
        size_t o = (size_t)(n0 + ty + j * 8) * K + k0 + tx;
        bf16 h = __float2bfloat16(v);
        hi[o] = h;
        lo[o] = __float2bfloat16(v - __bfloat162float(h));
    }
}

// ---------------------------------------------------------------------------
// Pipelined HMMA GEMMs: 512 thr, block 128x128x64, warp tile 32x32
// 3-stage cp.async multistage, ONE __syncthreads per k-chunk.
// ---------------------------------------------------------------------------
#define SA 72
#define GT_TILE2  (128 * SA * 2)          // 18432
#define GT_STG2   (4 * GT_TILE2)          // 73728
#define GEMM_SMEM (3 * GT_STG2)           // 221184

__device__ __forceinline__ void gemm_issue(
    uint32_t sb, int st, int kc, int bm, int bn, int tid, int K,
    const bf16* __restrict__ Ah, const bf16* __restrict__ Al,
    const bf16* __restrict__ Bh, const bf16* __restrict__ Bl) {
    int c0 = kc * 64;
    uint32_t base = sb + (uint32_t)st * GT_STG2;
#pragma unroll
    for (int it = 0; it < 2; it++) {
        int idx = tid + it * 512;
        int r = idx >> 3, cc = (idx & 7) * 8;
        size_t ga = (size_t)(bm * 128 + r) * K + c0 + cc;
        size_t gb = (size_t)(bn * 128 + r) * K + c0 + cc;
        uint32_t so = (uint32_t)(r * SA + cc) * 2;
        cp16(base + so, Ah + ga);
        cp16(base + GT_TILE2 + so, Al + ga);
        cp16(base + 2 * GT_TILE2 + so, Bh + gb);
        cp16(base + 3 * GT_TILE2 + so, Bl + gb);
    }
    CP_COMMIT();
}

#define GEMM_MAINLOOP(K_)                                                        \
    int a_row = wm * 32 + ((lane >> 3) & 1) * 8 + (lane & 7);                    \
    int a_kc  = (lane >> 4) * 8;                                                 \
    int b_row = wn * 32 + (lane >> 4) * 8 + (lane & 7);                          \
    int b_kc  = ((lane >> 3) & 1) * 8;                                           \
    float c[2][4][4];                                                            \
    _Pragma("unroll") for (int i = 0; i < 2; i++)                                \
    _Pragma("unroll") for (int j = 0; j < 4; j++)                                \
    _Pragma("unroll") for (int q = 0; q < 4; q++) c[i][j][q] = 0.f;              \
    const int NK = (K_) / 64;                                                    \
    gemm_issue(sb, 0, 0, bm, bn, tid, (K_), Ah, Al, Bh, Bl);                     \
    gemm_issue(sb, 1, 1, bm, bn, tid, (K_), Ah, Al, Bh, Bl);                     \
    for (int kc = 0; kc < NK; kc++) {                                            \
        if (kc + 1 < NK) CP_WAIT1(); else CP_WAIT0();                            \
        __syncthreads();                                                         \
        if (kc + 2 < NK)                                                         \
            gemm_issue(sb, (kc + 2) % 3, kc + 2, bm, bn, tid, (K_),              \
                       Ah, Al, Bh, Bl);                                          \
        uint32_t uAh = sb + (uint32_t)(kc % 3) * GT_STG2;                        \
        uint32_t uAl = uAh + GT_TILE2;                                           \
        uint32_t uBh = uAh + 2 * GT_TILE2;                                       \
        uint32_t uBl = uAh + 3 * GT_TILE2;                                       \
        _Pragma("unroll")                                                        \
        for (int ks = 0; ks < 4; ks++) {                                         \
            uint32_t ah[2][4], al[2][4], bh[2][4], bl[2][4];                     \
            _Pragma("unroll")                                                    \
            for (int ma = 0; ma < 2; ma++) {                                     \
                uint32_t off = ((a_row + ma * 16) * SA + a_kc + ks * 16) * 2;    \
                LDSM4(ah[ma][0], ah[ma][1], ah[ma][2], ah[ma][3], uAh + off);    \
                LDSM4(al[ma][0], al[ma][1], al[ma][2], al[ma][3], uAl + off);    \
            }                                                                    \
            _Pragma("unroll")                                                    \
            for (int nb2 = 0; nb2 < 2; nb2++) {                                  \
                uint32_t off = ((b_row + nb2 * 16) * SA + b_kc + ks * 16) * 2;   \
                LDSM4(bh[nb2][0], bh[nb2][1], bh[nb2][2], bh[nb2][3], uBh + off);\
                LDSM4(bl[nb2][0], bl[nb2][1], bl[nb2][2], bl[nb2][3], uBl + off);\
            }                                                                    \
            _Pragma("unroll")                                                    \
            for (int ma = 0; ma < 2; ma++)                                       \
            _Pragma("unroll")                                                    \
            for (int nb = 0; nb < 4; nb++) {                                     \
                int n2 = nb >> 1, o = (nb & 1) * 2;                              \
                MMA16816(c[ma][nb], ah[ma], bh[n2][o], bh[n2][o + 1]);           \
                MMA16816(c[ma][nb], ah[ma], bl[n2][o], bl[n2][o + 1]);           \
                MMA16816(c[ma][nb], al[ma], bh[n2][o], bh[n2][o + 1]);           \
            }                                                                    \
        }                                                                        \
    }                                                                            \
    __syncthreads();

__global__ void __launch_bounds__(512) gemm_mma_qkv(
    const bf16* __restrict__ Ah, const bf16* __restrict__ Al,
    const bf16* __restrict__ Bh, const bf16* __restrict__ Bl,
    const float* __restrict__ bias,
    bf16* __restrict__ qhi, bf16* __restrict__ qlo,
    bf16* __restrict__ khi, bf16* __restrict__ klo,
    bf16* __restrict__ vhi, bf16* __restrict__ vlo) {
    extern __shared__ char dyn[];
    uint32_t sb = smem_u32(dyn);
    int tid = threadIdx.x;
    int wid = tid >> 5, lane = tid & 31;
    int wm = wid & 3, wn = wid >> 2;
    int bm = blockIdx.y, bn = blockIdx.x;

    GEMM_MAINLOOP(D_MODEL)

    int r0 = bm * 128 + wm * 32 + (lane >> 2);
#pragma unroll
    for (int ma = 0; ma < 2; ma++) {
#pragma unroll
        for (int nb = 0; nb < 4; nb++) {
            int col = bn * 128 + wn * 32 + nb * 8 + (lane & 3) * 2;
            int hg = col >> 6;
            int sec = hg >> 4;
            int h = hg & 15;
            int c64 = col & 63;
            bf16* dh = (sec == 0) ? qhi : (sec == 1) ? khi : vhi;
            bf16* dl = (sec == 0) ? qlo : (sec == 1) ? klo : vlo;
            float bx = bias[col], by = bias[col + 1];
#pragma unroll
            for (int half = 0; half < 2; half++) {
                int row = r0 + ma * 16 + half * 8;
                int t = row & (T - 1), b = row >> 11;
                size_t idx = (((size_t)(b * NH + h)) * T + t) * DH + c64;
                float y0 = c[ma][nb][half * 2 + 0] + bx;
                float y1 = c[ma][nb][half * 2 + 1] + by;
                bf16 h0 = __float2bfloat16(y0);
                bf16 h1 = __float2bfloat16(y1);
                bf162 hv; hv.x = h0; hv.y = h1;
                bf162 lv;
                lv.x = __float2bfloat16(y0 - __bfloat162float(h0));
                lv.y = __float2bfloat16(y1 - __bfloat162float(h1));
                *(bf162*)&dh[idx] = hv;
                *(bf162*)&dl[idx] = lv;
            }
        }
    }
}

__global__ void __launch_bounds__(512) gemm_mma_out(
    const bf16* __restrict__ Ah, const bf16* __restrict__ Al,
    const bf16* __restrict__ Bh, const bf16* __restrict__ Bl,
    const float* __restrict__ bias, const float* __restrict__ res,
    float* __restrict__ C) {
    const int N = D_MODEL;
    extern __shared__ char dyn[];
    uint32_t sb = smem_u32(dyn);
    int tid = threadIdx.x;
    int wid = tid >> 5, lane = tid & 31;
    int wm = wid & 3, wn = wid >> 2;
    int bm = blockIdx.y, bn = blockIdx.x;

    GEMM_MAINLOOP(D_MODEL)

    int r0 = bm * 128 + wm * 32 + (lane >> 2);
#pragma unroll
    for (int ma = 0; ma < 2; ma++) {
#pragma unroll
        for (int nb = 0; nb < 4; nb++) {
            int col = bn * 128 + wn * 32 + nb * 8 + (lane & 3) * 2;
            int ra = r0 + ma * 16, rb = ra + 8;
            float2 o0, o1;
            o0.x = c[ma][nb][0] + bias[col];
            o0.y = c[ma][nb][1] + bias[col + 1];
            o1.x = c[ma][nb][2] + bias[col];
            o1.y = c[ma][nb][3] + bias[col + 1];
            float2 r2a = *(const float2*)&res[(size_t)ra * N + col];
            float2 r2b = *(const float2*)&res[(size_t)rb * N + col];
            o0.x += r2a.x; o0.y += r2a.y;
            o1.x += r2b.x; o1.y += r2b.y;
            *(float2*)&C[(size_t)ra * N + col] = o0;
            *(float2*)&C[(size_t)rb * N + col] = o1;
        }
    }
}

// ---------------------------------------------------------------------------
// Stats-only scores pass: per (row, 128-ktile) partial (m, sumexp). No S write.
// ---------------------------------------------------------------------------
#define SK 72
#define SCORES_SMEM (4 * 128 * SK * 2)

__global__ void __launch_bounds__(256) scores_stats(
    const bf16* __restrict__ qh, const bf16* __restrict__ ql,
    const bf16* __restrict__ kh, const bf16* __restrict__ kl,
    float2* __restrict__ part) {
    int kt = blockIdx.x, qt = blockIdx.y, bh = blockIdx.z;
    if (kt > qt) return;
    int tid = threadIdx.x;

    extern __shared__ char dyn[];
    bf16* sQh = (bf16*)dyn;
    bf16* sQl = sQh + 128 * SK;
    bf16* sKh = sQl + 128 * SK;
    bf16* sKl = sKh + 128 * SK;
    __shared__ float2 sstat[128][2];

    const bf16* qhb = qh + ((size_t)bh * T + qt * 128) * DH;
    const bf16* qlb = ql + ((size_t)bh * T + qt * 128) * DH;
    const bf16* khb = kh + ((size_t)bh * T + kt * 128) * DH;
    const bf16* klb = kl + ((size_t)bh * T + kt * 128) * DH;

#pragma unroll
    for (int it = 0; it < 4; it++) {
        int idx = tid + it * 256;
        int r = idx >> 3, cc = (idx & 7) * 8;
        int so = r * SK + cc;
        size_t go = (size_t)r * DH + cc;
        *(uint4*)&sQh[so] = *(const uint4*)&qhb[go];
        *(uint4*)&sQl[so] = *(const uint4*)&qlb[go];
        *(uint4*)&sKh[so] = *(const uint4*)&khb[go];
        *(uint4*)&sKl[so] = *(const uint4*)&klb[go];
    }
    __syncthreads();

    int wid = tid >> 5, lane = tid & 31;
    int wm = wid & 3, wn = wid >> 2;
    uint32_t uQh = smem_u32(sQh), uQl = smem_u32(sQl);
    uint32_t uKh = smem_u32(sKh), uKl = smem_u32(sKl);

    int a_row = wm * 32 + ((lane >> 3) & 1) * 8 + (lane & 7);
    int a_kc  = (lane >> 4) * 8;
    int b_row = wn * 64 + (lane >> 4) * 8 + (lane & 7);
    int b_kc  = ((lane >> 3) & 1) * 8;

    float c[2][8][4];
#pragma unroll
    for (int i = 0; i < 2; i++)
#pragma unroll
        for (int j = 0; j < 8; j++)
#pragma unroll
            for (int q = 0; q < 4; q++) c[i][j][q] = 0.f;

#pragma unroll
    for (int ks = 0; ks < 4; ks++) {
        uint32_t ah[2][4], al[2][4], bh2[4][4], bl2[4][4];
#pragma unroll
        for (int ma = 0; ma < 2; ma++) {
            uint32_t off = ((a_row + ma * 16) * SK + a_kc + ks * 16) * 2;
            LDSM4(ah[ma][0], ah[ma][1], ah[ma][2], ah[ma][3], uQh + off);
            LDSM4(al[ma][0], al[ma][1], al[ma][2], al[ma][3], uQl + off);
        }
#pragma unroll
        for (int nb2 = 0; nb2 < 4; nb2++) {
            uint32_t off = ((b_row + nb2 * 16) * SK + b_kc + ks * 16) * 2;
            LDSM4(bh2[nb2][0], bh2[nb2][1], bh2[nb2][2], bh2[nb2][3], uKh + off);
            LDSM4(bl2[nb2][0], bl2[nb2][1], bl2[nb2][2], bl2[nb2][3], uKl + off);
        }
#pragma unroll
        for (int ma = 0; ma < 2; ma++)
#pragma unroll
            for (int nb = 0; nb < 8; nb++) {
                int n2 = nb >> 1, o = (nb & 1) * 2;
                MMA16816(c[ma][nb], ah[ma], bh2[n2][o], bh2[n2][o + 1]);
                MMA16816(c[ma][nb], ah[ma], bl2[n2][o], bl2[n2][o + 1]);
                MMA16816(c[ma][nb], al[ma], bh2[n2][o], bh2[n2][o + 1]);
            }
    }

    bool diag = (qt == kt);
#pragma unroll
    for (int ma = 0; ma < 2; ma++) {
#pragma unroll
        for (int half = 0; half < 2; half++) {
            int lrow = wm * 32 + ma * 16 + half * 8 + (lane >> 2);
            float vv[8][2];
#pragma unroll
            for (int nb = 0; nb < 8; nb++) {
                int colc = wn * 64 + nb * 8 + (lane & 3) * 2;
                float v0 = c[ma][nb][half * 2 + 0] * 0.125f;
                float v1 = c[ma][nb][half * 2 + 1] * 0.125f;
                if (diag) {
                    if (colc > lrow) v0 = -1e30f;
                    if (colc + 1 > lrow) v1 = -1e30f;
                }
                vv[nb][0] = v0; vv[nb][1] = v1;
            }
            float mt = -1e30f;
#pragma unroll
            for (int nb = 0; nb < 8; nb++) {
                mt = fmaxf(mt, vv[nb][0]);
                mt = fmaxf(mt, vv[nb][1]);
            }
            float st = 0.f;
#pragma unroll
            for (int nb = 0; nb < 8; nb++) {
                st += __expf(vv[nb][0] - mt);
                st += __expf(vv[nb][1] - mt);
            }
#pragma unroll
            for (int o = 1; o < 4; o <<= 1) {
                float om = __shfl_xor_sync(~0u, mt, o);
                float os = __shfl_xor_sync(~0u, st, o);
                ms_merge(mt, st, om, os);
            }
            if ((lane & 3) == 0) sstat[lrow][wn] = make_float2(mt, st);
        }
    }
    __syncthreads();
    if (tid < 128) {
        float2 p0 = sstat[tid][0], p1 = sstat[tid][1];
        float m = p0.x, s = p0.y;
        ms_merge(m, s, p1.x, p1.y);
        part[((size_t)bh * T + qt * 128 + tid) * 16 + kt] = make_float2(m, s);
    }
}

// ---------------------------------------------------------------------------
// Reduce per-row partials -> (m, 1/sum)
// ---------------------------------------------------------------------------
__global__ void reduce_stats(const float2* __restrict__ part,
                             float* __restrict__ mA, float* __restrict__ invA) {
    int row = blockIdx.x * 256 + threadIdx.x;
    int r = row & (T - 1);
    int nkb = (r >> 7) + 1;
    float m = -1e30f, s = 0.f;
    const float2* p = part + (size_t)row * 16;
    for (int i = 0; i < nkb; i++) {
        float2 v = p[i];
        ms_merge(m, s, v.x, v.y);
    }
    mA[row] = m;
    invA[row] = 1.f / s;
}

// ---------------------------------------------------------------------------
// Fused av: recompute S (Q persistent in regs, K/V 64-chunks via cp.async),
// normalize in registers, write P fp32 to attn, repack c-frags -> a-frags
// (bf16 hi/lo), MMA with V -> O. Zero-fill upper triangle.
// 256 threads, 8 warps, each warp owns 16 q-rows. (2 CTAs/SM at 110KB smem.)
// ---------------------------------------------------------------------------
#define FK 72
#define FA_QT2  (128 * FK * 2)            // 18432
#define FA_KT2  (64 * FK * 2)             // 9216
#define FA_STG  (4 * FA_KT2)              // 36864 (Kh,Kl,Vh,Vl)
#define FA_KV   (2 * FA_QT2)              // 36864
#define FA_SMEM (FA_KV + 2 * FA_STG)      // 110592

__device__ __forceinline__ void fa_issue_kv(
    uint32_t sb, int st, int kt, int tid,
    const bf16* __restrict__ kh, const bf16* __restrict__ kl,
    const bf16* __restrict__ vh, const bf16* __restrict__ vl) {
    uint32_t base = sb + FA_KV + (uint32_t)st * FA_STG;
#pragma unroll
    for (int p = 0; p < 2; p++) {
        int idx = tid + p * 256;
        int r = idx >> 3, cc = (idx & 7) * 8;
        size_t g = (size_t)(kt * 64 + r) * DH + cc;
        uint32_t so = (uint32_t)(r * FK + cc) * 2;
        cp16(base + so, kh + g);
        cp16(base + FA_KT2 + so, kl + g);
        cp16(base + 2 * FA_KT2 + so, vh + g);
        cp16(base + 3 * FA_KT2 + so, vl + g);
    }
    CP_COMMIT();
}

__global__ void __launch_bounds__(256) av_fused(
    const bf16* __restrict__ qhA, const bf16* __restrict__ qlA,
    const bf16* __restrict__ khA, const bf16* __restrict__ klA,
    const bf16* __restrict__ vhA, const bf16* __restrict__ vlA,
    const float* __restrict__ mA, const float* __restrict__ invA,
    float* __restrict__ attn,
    bf16* __restrict__ ohi, bf16* __restrict__ olo) {
    int qt = blockIdx.x, bh = blockIdx.y;
    int b = bh >> 4, h = bh & 15;
    int tid = threadIdx.x;
    int wid = tid >> 5, lane = tid & 31;

    extern __shared__ char dyn[];
    uint32_t sb = smem_u32(dyn);

    const bf16* qh = qhA + ((size_t)bh * T + qt * 128) * DH;
    const bf16* ql = qlA + ((size_t)bh * T + qt * 128) * DH;
    const bf16* kh = khA + (size_t)bh * T * DH;
    const bf16* kl = klA + (size_t)bh * T * DH;
    const bf16* vh = vhA + (size_t)bh * T * DH;
    const bf16* vl = vlA + (size_t)bh * T * DH;
    float* sblk = attn + ((size_t)bh * T + qt * 128) * T;

    int lr0 = wid * 16 + (lane >> 2);
    int lr1 = lr0 + 8;
    int qrow0 = qt * 128 + lr0, qrow1 = qt * 128 + lr1;
    float m0 = mA[bh * T + qrow0], iv0 = invA[bh * T + qrow0];
    float m1 = mA[bh * T + qrow1], iv1 = invA[bh * T + qrow1];

    {
#pragma unroll
        for (int p = 0; p < 4; p++) {
            int idx = tid + p * 256;
            int r = idx >> 3, cc = (idx & 7) * 8;
            size_t g = (size_t)r * DH + cc;
            uint32_t so = (uint32_t)(r * FK + cc) * 2;
            cp16(sb + so, qh + g);
            cp16(sb + FA_QT2 + so, ql + g);
        }
        CP_COMMIT();
    }
    fa_issue_kv(sb, 0, 0, tid, kh, kl, vh, vl);

    int a_row = wid * 16 + ((lane >> 3) & 1) * 8 + (lane & 7);
    int a_kc  = (lane >> 4) * 8;
    int b_row8 = (lane >> 4) * 8 + (lane & 7);
    int b_kc  = ((lane >> 3) & 1) * 8;
    int v_k   = lane & 15;
    int v_n   = (lane >> 4) * 8;

    uint32_t qa_h[4][4], qa_l[4][4];
    float o[8][4];
#pragma unroll
    for (int i = 0; i < 8; i++)
#pragma unroll
        for (int q = 0; q < 4; q++) o[i][q] = 0.f;

    int nk = 2 * qt + 2;
    for (int kt = 0; kt < nk; kt++) {
        if (kt + 1 < nk) { fa_issue_kv(sb, (kt + 1) & 1, kt + 1, tid, kh, kl, vh, vl); CP_WAIT1(); }
        else CP_WAIT0();
        __syncthreads();

        if (kt == 0) {
#pragma unroll
            for (int ks = 0; ks < 4; ks++) {
                uint32_t off = (a_row * FK + a_kc + ks * 16) * 2;
                LDSM4(qa_h[ks][0], qa_h[ks][1], qa_h[ks][2], qa_h[ks][3], sb + off);
                LDSM4(qa_l[ks][0], qa_l[ks][1], qa_l[ks][2], qa_l[ks][3], sb + FA_QT2 + off);
            }
        }

        uint32_t uKh = sb + FA_KV + (uint32_t)(kt & 1) * FA_STG;
        uint32_t uKl = uKh + FA_KT2;
        uint32_t uVh = uKh + 2 * FA_KT2;
        uint32_t uVl = uKh + 3 * FA_KT2;

        float s[8][4];
#pragma unroll
        for (int i = 0; i < 8; i++)
#pragma unroll
            for (int q = 0; q < 4; q++) s[i][q] = 0.f;

#pragma unroll
        for (int ks = 0; ks < 4; ks++) {
            uint32_t kbh[4][4], kbl[4][4];
#pragma unroll
            for (int nb2 = 0; nb2 < 4; nb2++) {
                uint32_t off = ((nb2 * 16 + b_row8) * FK + b_kc + ks * 16) * 2;
                LDSM4(kbh[nb2][0], kbh[nb2][1], kbh[nb2][2], kbh[nb2][3], uKh + off);
                LDSM4(kbl[nb2][0], kbl[nb2][1], kbl[nb2][2], kbl[nb2][3], uKl + off);
            }
#pragma unroll
            for (int nb = 0; nb < 8; nb++) {
                int n2 = nb >> 1, oo = (nb & 1) * 2;
                MMA16816(s[nb], qa_h[ks], kbh[n2][oo], kbh[n2][oo + 1]);
                MMA16816(s[nb], qa_h[ks], kbl[n2][oo], kbl[n2][oo + 1]);
                MMA16816(s[nb], qa_l[ks], kbh[n2][oo], kbh[n2][oo + 1]);
            }
        }

        uint32_t pa_h[4][4], pa_l[4][4];
#pragma unroll
        for (int nb = 0; nb < 8; nb++) {
            int kcol = kt * 64 + nb * 8 + (lane & 3) * 2;
            float p0 = (kcol     <= qrow0) ? __expf(s[nb][0] * 0.125f - m0) * iv0 : 0.f;
            float p1 = (kcol + 1 <= qrow0) ? __expf(s[nb][1] * 0.125f - m0) * iv0 : 0.f;
            float p2 = (kcol     <= qrow1) ? __expf(s[nb][2] * 0.125f - m1) * iv1 : 0.f;
            float p3 = (kcol + 1 <= qrow1) ? __expf(s[nb][3] * 0.125f - m1) * iv1 : 0.f;
            float2 w0; w0.x = p0; w0.y = p1;
            float2 w1; w1.x = p2; w1.y = p3;
            *(float2*)&sblk[(size_t)lr0 * T + kcol] = w0;
            *(float2*)&sblk[(size_t)lr1 * T + kcol] = w1;
            bf16 h0 = __float2bfloat16(p0), h1b = __float2bfloat16(p1);
            bf16 h2 = __float2bfloat16(p2), h3 = __float2bfloat16(p3);
            float l0f = p0 - __bfloat162float(h0), l1f = p1 - __bfloat162float(h1b);
            float l2f = p2 - __bfloat162float(h2), l3f = p3 - __bfloat162float(h3);
            int j = nb >> 1, hf = (nb & 1) * 2;
            bf162 t0; t0.x = h0; t0.y = h1b;
            bf162 t1; t1.x = h2; t1.y = h3;
            pa_h[j][hf]     = *(uint32_t*)&t0;
            pa_h[j][hf + 1] = *(uint32_t*)&t1;
            pa_l[j][hf]     = packbf(l0f, l1f);
            pa_l[j][hf + 1] = packbf(l2f, l3f);
        }

#pragma unroll
        for (int j = 0; j < 4; j++) {
            uint32_t vbh[4][4], vbl[4][4];
#pragma unroll
            for (int ns = 0; ns < 4; ns++) {
                uint32_t off = ((j * 16 + v_k) * FK + ns * 16 + v_n) * 2;
                LDSM4T(vbh[ns][0], vbh[ns][1], vbh[ns][2], vbh[ns][3], uVh + off);
                LDSM4T(vbl[ns][0], vbl[ns][1], vbl[ns][2], vbl[ns][3], uVl + off);
            }
#pragma unroll
            for (int nb = 0; nb < 8; nb++) {
                int n2 = nb >> 1, oo = (nb & 1) * 2;
                MMA16816(o[nb], pa_h[j], vbh[n2][oo], vbh[n2][oo + 1]);
                MMA16816(o[nb], pa_h[j], vbl[n2][oo], vbl[n2][oo + 1]);
                MMA16816(o[nb], pa_l[j], vbh[n2][oo], vbh[n2][oo + 1]);
            }
        }
        __syncthreads();
    }

    {
        int c0u = (qt + 1) * 128;
        int r = tid >> 1, hf = tid & 1;
        float4 z = make_float4(0.f, 0.f, 0.f, 0.f);
        for (int cc = c0u + hf * 4; cc < T; cc += 8)
            *(float4*)&sblk[(size_t)r * T + cc] = z;
    }

#pragma unroll
    for (int nb = 0; nb < 8; nb++) {
        int d = nb * 8 + (lane & 3) * 2;
        size_t i0 = ((size_t)(b * T + qrow0)) * D_MODEL + h * DH + d;
        size_t i1 = ((size_t)(b * T + qrow1)) * D_MODEL + h * DH + d;
        float y0 = o[nb][0], y1 = o[nb][1], y2 = o[nb][2], y3 = o[nb][3];
        bf16 h0 = __float2bfloat16(y0), h1b = __float2bfloat16(y1);
        bf16 h2 = __float2bfloat16(y2), h3 = __float2bfloat16(y3);
        bf162 hv0; hv0.x = h0; hv0.y = h1b;
        bf162 hv1; hv1.x = h2; hv1.y = h3;
        *(bf162*)&ohi[i0] = hv0;
        *(bf162*)&ohi[i1] = hv1;
        bf162 lv0, lv1;
        lv0.x = __float2bfloat16(y0 - __bfloat162float(h0));
        lv0.y = __float2bfloat16(y1 - __bfloat162float(h1b));
        lv1.x = __float2bfloat16(y2 - __bfloat162float(h2));
        lv1.y = __float2bfloat16(y3 - __bfloat162float(h3));
        *(bf162*)&olo[i0] = lv0;
        *(bf162*)&olo[i1] = lv1;
    }
}

// ---------------------------------------------------------------------------
extern "C" void kernel_launch(void* const* d_in, const int* in_sizes, int n_in,
                              void* d_out, int out_size) {
    (void)in_sizes; (void)n_in; (void)out_size;
    const float* x     = (const float*)d_in[0];
    const float* ln_g  = (const float*)d_in[1];
    const float* ln_b  = (const float*)d_in[2];
    const float* qkv_w = (const float*)d_in[3];
    const float* qkv_b = (const float*)d_in[4];
    const float* out_w = (const float*)d_in[5];
    const float* out_b = (const float*)d_in[6];

    float* xout = (float*)d_out;
    float* attn = xout + (size_t)BT * D_MODEL;

    static bf16 *p_hhi = nullptr, *p_hlo, *p_wqh, *p_wql, *p_woh, *p_wol;
    static bf16 *p_qh, *p_ql, *p_kh, *p_kl, *p_vh, *p_vl, *p_aoh, *p_aol;
    static float2* p_part;
    static float *p_m, *p_inv;
    if (!p_hhi) {
        cudaGetSymbolAddress((void**)&p_hhi, g_h_hi);
        cudaGetSymbolAddress((void**)&p_hlo, g_h_lo);
        cudaGetSymbolAddress((void**)&p_wqh, g_wq_hi);
        cudaGetSymbolAddress((void**)&p_wql, g_wq_lo);
        cudaGetSymbolAddress((void**)&p_woh, g_wo_hi);
        cudaGetSymbolAddress((void**)&p_wol, g_wo_lo);
        cudaGetSymbolAddress((void**)&p_qh, g_q_hi);
        cudaGetSymbolAddress((void**)&p_ql, g_q_lo);
        cudaGetSymbolAddress((void**)&p_kh, g_k_hi);
        cudaGetSymbolAddress((void**)&p_kl, g_k_lo);
        cudaGetSymbolAddress((void**)&p_vh, g_v_hi);
        cudaGetSymbolAddress((void**)&p_vl, g_v_lo);
        cudaGetSymbolAddress((void**)&p_aoh, g_ao_hi);
        cudaGetSymbolAddress((void**)&p_aol, g_ao_lo);
        cudaGetSymbolAddress((void**)&p_part, g_part);
        cudaGetSymbolAddress((void**)&p_m, g_m);
        cudaGetSymbolAddress((void**)&p_inv, g_inv);
        cudaFuncSetAttribute(gemm_mma_qkv, cudaFuncAttributeMaxDynamicSharedMemorySize, GEMM_SMEM);
        cudaFuncSetAttribute(gemm_mma_out, cudaFuncAttributeMaxDynamicSharedMemorySize, GEMM_SMEM);
        cudaFuncSetAttribute(scores_stats, cudaFuncAttributeMaxDynamicSharedMemorySize, SCORES_SMEM);
        cudaFuncSetAttribute(av_fused, cudaFuncAttributeMaxDynamicSharedMemorySize, FA_SMEM);
    }

    ln_kernel<<<BT, 256>>>(x, ln_g, ln_b, p_hhi, p_hlo);
    tsplit_kernel<<<dim3(QKV_N / 32, D_MODEL / 32), dim3(32, 8)>>>(qkv_w, p_wqh, p_wql, D_MODEL, QKV_N);
    tsplit_kernel<<<dim3(D_MODEL / 32, D_MODEL / 32), dim3(32, 8)>>>(out_w, p_woh, p_wol, D_MODEL, D_MODEL);

    gemm_mma_qkv<<<dim3(QKV_N / 128, BT / 128), 512, GEMM_SMEM>>>(
        p_hhi, p_hlo, p_wqh, p_wql, qkv_b, p_qh, p_ql, p_kh, p_kl, p_vh, p_vl);

    scores_stats<<<dim3(16, 16, 32), 256, SCORES_SMEM>>>(p_qh, p_ql, p_kh, p_kl, p_part);
    reduce_stats<<<(32 * T) / 256, 256>>>(p_part, p_m, p_inv);
    av_fused<<<dim3(16, 32), 256, FA_SMEM>>>(p_qh, p_ql, p_kh, p_kl, p_vh, p_vl,
                                             p_m, p_inv, attn, p_aoh, p_aol);

    gemm_mma_out<<<dim3(D_MODEL / 128, BT / 128), 512, GEMM_SMEM>>>(
        p_aoh, p_aol, p_woh, p_wol, out_b, x, xout);
}

// round 14
// speedup vs baseline: 1.5562x; 1.5562x over previous
#include <cuda_runtime.h>
#include <cuda_bf16.h>
#include <cstdint>
#include <math.h>

#define D_MODEL 1024
#define NH      16
#define DH      64
#define BATCH   2
#define T       2048
#define BT      4096
#define QKV_N   3072

typedef __nv_bfloat16 bf16;
typedef __nv_bfloat162 bf162;

// ---------------------------------------------------------------------------
// Scratch
// ---------------------------------------------------------------------------
__device__ bf16 g_h_hi[(size_t)BT * D_MODEL];
__device__ bf16 g_h_lo[(size_t)BT * D_MODEL];
__device__ bf16 g_wq_hi[(size_t)QKV_N * D_MODEL];
__device__ bf16 g_wq_lo[(size_t)QKV_N * D_MODEL];
__device__ bf16 g_wo_hi[(size_t)D_MODEL * D_MODEL];
__device__ bf16 g_wo_lo[(size_t)D_MODEL * D_MODEL];
__device__ bf16 g_q_hi[(size_t)32 * T * DH];
__device__ bf16 g_q_lo[(size_t)32 * T * DH];
__device__ bf16 g_k_hi[(size_t)32 * T * DH];
__device__ bf16 g_k_lo[(size_t)32 * T * DH];
__device__ bf16 g_v_hi[(size_t)32 * T * DH];
__device__ bf16 g_v_lo[(size_t)32 * T * DH];
__device__ bf16 g_ao_hi[(size_t)BT * D_MODEL];
__device__ bf16 g_ao_lo[(size_t)BT * D_MODEL];
__device__ float2 g_part[(size_t)32 * T * 16];
__device__ float  g_m[(size_t)32 * T];
__device__ float  g_inv[(size_t)32 * T];

// ---------------------------------------------------------------------------
// Helpers
// ---------------------------------------------------------------------------
__device__ __forceinline__ uint32_t smem_u32(const void* p) {
    uint32_t a;
    asm("{ .reg .u64 t; cvta.to.shared.u64 t, %1; cvt.u32.u64 %0, t; }" : "=r"(a) : "l"(p));
    return a;
}
__device__ __forceinline__ void cp16(uint32_t dst, const void* src) {
    asm volatile("cp.async.cg.shared.global [%0], [%1], 16;" :: "r"(dst), "l"(src));
}
#define CP_COMMIT() asm volatile("cp.async.commit_group;" ::: "memory")
#define CP_WAIT0()  asm volatile("cp.async.wait_group 0;" ::: "memory")
#define CP_WAIT1()  asm volatile("cp.async.wait_group 1;" ::: "memory")
#define LDSM4(r0, r1, r2, r3, addr)                                              \
    asm volatile("ldmatrix.sync.aligned.m8n8.x4.shared.b16 {%0,%1,%2,%3}, [%4];" \
                 : "=r"(r0), "=r"(r1), "=r"(r2), "=r"(r3) : "r"(addr))
#define LDSM4T(r0, r1, r2, r3, addr)                                                   \
    asm volatile("ldmatrix.sync.aligned.m8n8.x4.trans.shared.b16 {%0,%1,%2,%3}, [%4];" \
                 : "=r"(r0), "=r"(r1), "=r"(r2), "=r"(r3) : "r"(addr))
#define MMA16816(c, a, b0, b1)                                                   \
    asm volatile("mma.sync.aligned.m16n8k16.row.col.f32.bf16.bf16.f32 "          \
                 "{%0,%1,%2,%3}, {%4,%5,%6,%7}, {%8,%9}, {%0,%1,%2,%3};"         \
                 : "+f"((c)[0]), "+f"((c)[1]), "+f"((c)[2]), "+f"((c)[3])        \
                 : "r"((a)[0]), "r"((a)[1]), "r"((a)[2]), "r"((a)[3]),           \
                   "r"(b0), "r"(b1))

__device__ __forceinline__ void ms_merge(float& m, float& s, float om, float os) {
    float M = fmaxf(m, om);
    s = s * __expf(m - M) + os * __expf(om - M);
    m = M;
}
__device__ __forceinline__ uint32_t packbf(float a, float b) {
    bf162 v; v.x = __float2bfloat16(a); v.y = __float2bfloat16(b);
    return *(uint32_t*)&v;
}

// ---------------------------------------------------------------------------
// LayerNorm -> bf16 hi/lo split
// ---------------------------------------------------------------------------
__global__ void ln_kernel(const float* __restrict__ x, const float* __restrict__ gam,
                          const float* __restrict__ bet,
                          bf16* __restrict__ ohi, bf16* __restrict__ olo) {
    int row = blockIdx.x;
    const float* xr = x + (size_t)row * D_MODEL;
    float v[4];
    float s = 0.f, s2 = 0.f;
#pragma unroll
    for (int i = 0; i < 4; i++) {
        v[i] = xr[threadIdx.x + i * 256];
        s += v[i]; s2 += v[i] * v[i];
    }
#pragma unroll
    for (int o = 16; o > 0; o >>= 1) {
        s  += __shfl_xor_sync(~0u, s, o);
        s2 += __shfl_xor_sync(~0u, s2, o);
    }
    __shared__ float rs[8], rs2[8];
    int wid = threadIdx.x >> 5, lid = threadIdx.x & 31;
    if (lid == 0) { rs[wid] = s; rs2[wid] = s2; }
    __syncthreads();
    s = 0.f; s2 = 0.f;
#pragma unroll
    for (int i = 0; i < 8; i++) { s += rs[i]; s2 += rs2[i]; }
    float mu  = s * (1.f / D_MODEL);
    float var = s2 * (1.f / D_MODEL) - mu * mu;
    float inv = rsqrtf(var + 1e-5f);
#pragma unroll
    for (int i = 0; i < 4; i++) {
        int c = threadIdx.x + i * 256;
        float y = (v[i] - mu) * inv * gam[c] + bet[c];
        bf16 h = __float2bfloat16(y);
        ohi[(size_t)row * D_MODEL + c] = h;
        olo[(size_t)row * D_MODEL + c] = __float2bfloat16(y - __bfloat162float(h));
    }
}

// ---------------------------------------------------------------------------
// Transpose + bf16 split: W[K][N] -> out[N][K]
// ---------------------------------------------------------------------------
__global__ void tsplit_kernel(const float* __restrict__ W,
                              bf16* __restrict__ hi, bf16* __restrict__ lo,
                              int K, int N) {
    __shared__ float t[32][33];
    int n0 = blockIdx.x * 32, k0 = blockIdx.y * 32;
    int tx = threadIdx.x, ty = threadIdx.y;
#pragma unroll
    for (int j = 0; j < 4; j++)
        t[ty + j * 8][tx] = W[(size_t)(k0 + ty + j * 8) * N + n0 + tx];
    __syncthreads();
#pragma unroll
    for (int j = 0; j < 4; j++) {
        float v = t[tx][ty + j * 8];
        size_t o = (size_t)(n0 + ty + j * 8) * K + k0 + tx;
        bf16 h = __float2bfloat16(v);
        hi[o] = h;
        lo[o] = __float2bfloat16(v - __bfloat162float(h));
    }
}

// ---------------------------------------------------------------------------
// QKV GEMM: 768 threads, block 128x192x64, warp grid 4x6, warp tile 32x32.
// 2-stage cp.async (proven R10 structure).
// ---------------------------------------------------------------------------
#define SA 72
#define QK_AT   (128 * SA * 2)            // 18432
#define QK_BT   (192 * SA * 2)            // 27648
#define QK_STG  (2 * QK_AT + 2 * QK_BT)   // 92160
#define QKV_SMEM (2 * QK_STG)             // 184320

__device__ __forceinline__ void qkv_issue(
    uint32_t sb, int st, int kc, int bm, int bn, int tid,
    const bf16* __restrict__ Ah, const bf16* __restrict__ Al,
    const bf16* __restrict__ Bh, const bf16* __restrict__ Bl) {
    const int K = D_MODEL;
    int c0 = kc * 64;
    uint32_t base = sb + (uint32_t)st * QK_STG;
    // A tile: 128x64 -> 1024 cp16 slots over 768 threads
#pragma unroll
    for (int it = 0; it < 2; it++) {
        int idx = tid + it * 768;
        if (idx < 1024) {
            int r = idx >> 3, cc = (idx & 7) * 8;
            size_t ga = (size_t)(bm * 128 + r) * K + c0 + cc;
            uint32_t so = (uint32_t)(r * SA + cc) * 2;
            cp16(base + so, Ah + ga);
            cp16(base + QK_AT + so, Al + ga);
        }
    }
    // B tile: 192x64 -> 1536 cp16 slots = 2 per thread exactly
#pragma unroll
    for (int it = 0; it < 2; it++) {
        int idx = tid + it * 768;
        int r = idx >> 3, cc = (idx & 7) * 8;
        size_t gb = (size_t)(bn * 192 + r) * K + c0 + cc;
        uint32_t so = (uint32_t)(r * SA + cc) * 2;
        cp16(base + 2 * QK_AT + so, Bh + gb);
        cp16(base + 2 * QK_AT + QK_BT + so, Bl + gb);
    }
    CP_COMMIT();
}

__global__ void __launch_bounds__(768) gemm_mma_qkv(
    const bf16* __restrict__ Ah, const bf16* __restrict__ Al,
    const bf16* __restrict__ Bh, const bf16* __restrict__ Bl,
    const float* __restrict__ bias,
    bf16* __restrict__ qhi, bf16* __restrict__ qlo,
    bf16* __restrict__ khi, bf16* __restrict__ klo,
    bf16* __restrict__ vhi, bf16* __restrict__ vlo) {
    extern __shared__ char dyn[];
    uint32_t sb = smem_u32(dyn);
    int tid = threadIdx.x;
    int wid = tid >> 5, lane = tid & 31;
    int wm = wid & 3, wn = wid >> 2;          // 4 (M) x 6 (N)
    int bm = blockIdx.y, bn = blockIdx.x;

    int a_row = wm * 32 + ((lane >> 3) & 1) * 8 + (lane & 7);
    int a_kc  = (lane >> 4) * 8;
    int b_row = wn * 32 + (lane >> 4) * 8 + (lane & 7);
    int b_kc  = ((lane >> 3) & 1) * 8;

    float c[2][4][4];
#pragma unroll
    for (int i = 0; i < 2; i++)
#pragma unroll
        for (int j = 0; j < 4; j++)
#pragma unroll
            for (int q = 0; q < 4; q++) c[i][j][q] = 0.f;

    const int NK = D_MODEL / 64;
    qkv_issue(sb, 0, 0, bm, bn, tid, Ah, Al, Bh, Bl);
    for (int kc = 0; kc < NK; kc++) {
        if (kc + 1 < NK) { qkv_issue(sb, (kc + 1) & 1, kc + 1, bm, bn, tid, Ah, Al, Bh, Bl); CP_WAIT1(); }
        else CP_WAIT0();
        __syncthreads();
        uint32_t uAh = sb + (uint32_t)(kc & 1) * QK_STG;
        uint32_t uAl = uAh + QK_AT;
        uint32_t uBh = uAh + 2 * QK_AT;
        uint32_t uBl = uBh + QK_BT;
#pragma unroll
        for (int ks = 0; ks < 4; ks++) {
            uint32_t ah[2][4], al[2][4], bh[2][4], bl[2][4];
#pragma unroll
            for (int ma = 0; ma < 2; ma++) {
                uint32_t off = ((a_row + ma * 16) * SA + a_kc + ks * 16) * 2;
                LDSM4(ah[ma][0], ah[ma][1], ah[ma][2], ah[ma][3], uAh + off);
                LDSM4(al[ma][0], al[ma][1], al[ma][2], al[ma][3], uAl + off);
            }
#pragma unroll
            for (int nb2 = 0; nb2 < 2; nb2++) {
                uint32_t off = ((b_row + nb2 * 16) * SA + b_kc + ks * 16) * 2;
                LDSM4(bh[nb2][0], bh[nb2][1], bh[nb2][2], bh[nb2][3], uBh + off);
                LDSM4(bl[nb2][0], bl[nb2][1], bl[nb2][2], bl[nb2][3], uBl + off);
            }
#pragma unroll
            for (int ma = 0; ma < 2; ma++)
#pragma unroll
                for (int nb = 0; nb < 4; nb++) {
                    int n2 = nb >> 1, o = (nb & 1) * 2;
                    MMA16816(c[ma][nb], ah[ma], bh[n2][o], bh[n2][o + 1]);
                    MMA16816(c[ma][nb], ah[ma], bl[n2][o], bl[n2][o + 1]);
                    MMA16816(c[ma][nb], al[ma], bh[n2][o], bh[n2][o + 1]);
                }
        }
        __syncthreads();
    }

    int r0 = bm * 128 + wm * 32 + (lane >> 2);
#pragma unroll
    for (int ma = 0; ma < 2; ma++) {
#pragma unroll
        for (int nb = 0; nb < 4; nb++) {
            int col = bn * 192 + wn * 32 + nb * 8 + (lane & 3) * 2;
            int hg = col >> 6;
            int sec = hg >> 4;
            int h = hg & 15;
            int c64 = col & 63;
            bf16* dh = (sec == 0) ? qhi : (sec == 1) ? khi : vhi;
            bf16* dl = (sec == 0) ? qlo : (sec == 1) ? klo : vlo;
            float bx = bias[col], by = bias[col + 1];
#pragma unroll
            for (int half = 0; half < 2; half++) {
                int row = r0 + ma * 16 + half * 8;
                int t = row & (T - 1), b = row >> 11;
                size_t idx = (((size_t)(b * NH + h)) * T + t) * DH + c64;
                float y0 = c[ma][nb][half * 2 + 0] + bx;
                float y1 = c[ma][nb][half * 2 + 1] + by;
                bf16 h0 = __float2bfloat16(y0);
                bf16 h1 = __float2bfloat16(y1);
                bf162 hv; hv.x = h0; hv.y = h1;
                bf162 lv;
                lv.x = __float2bfloat16(y0 - __bfloat162float(h0));
                lv.y = __float2bfloat16(y1 - __bfloat162float(h1));
                *(bf162*)&dh[idx] = hv;
                *(bf162*)&dl[idx] = lv;
            }
        }
    }
}

// ---------------------------------------------------------------------------
// Out-proj GEMM: R10 proven 512-thread, 128x128x64, 2-stage.
// ---------------------------------------------------------------------------
#define GT_TILE2  (128 * SA * 2)          // 18432
#define GT_STG2   (4 * GT_TILE2)          // 73728
#define GEMM_SMEM (2 * GT_STG2)           // 147456

__device__ __forceinline__ void gemm_issue(
    uint32_t sb, int st, int kc, int bm, int bn, int tid, int K,
    const bf16* __restrict__ Ah, const bf16* __restrict__ Al,
    const bf16* __restrict__ Bh, const bf16* __restrict__ Bl) {
    int c0 = kc * 64;
    uint32_t base = sb + (uint32_t)st * GT_STG2;
#pragma unroll
    for (int it = 0; it < 2; it++) {
        int idx = tid + it * 512;
        int r = idx >> 3, cc = (idx & 7) * 8;
        size_t ga = (size_t)(bm * 128 + r) * K + c0 + cc;
        size_t gb = (size_t)(bn * 128 + r) * K + c0 + cc;
        uint32_t so = (uint32_t)(r * SA + cc) * 2;
        cp16(base + so, Ah + ga);
        cp16(base + GT_TILE2 + so, Al + ga);
        cp16(base + 2 * GT_TILE2 + so, Bh + gb);
        cp16(base + 3 * GT_TILE2 + so, Bl + gb);
    }
    CP_COMMIT();
}

__global__ void __launch_bounds__(512) gemm_mma_out(
    const bf16* __restrict__ Ah, const bf16* __restrict__ Al,
    const bf16* __restrict__ Bh, const bf16* __restrict__ Bl,
    const float* __restrict__ bias, const float* __restrict__ res,
    float* __restrict__ C) {
    const int N = D_MODEL;
    extern __shared__ char dyn[];
    uint32_t sb = smem_u32(dyn);
    int tid = threadIdx.x;
    int wid = tid >> 5, lane = tid & 31;
    int wm = wid & 3, wn = wid >> 2;
    int bm = blockIdx.y, bn = blockIdx.x;

    int a_row = wm * 32 + ((lane >> 3) & 1) * 8 + (lane & 7);
    int a_kc  = (lane >> 4) * 8;
    int b_row = wn * 32 + (lane >> 4) * 8 + (lane & 7);
    int b_kc  = ((lane >> 3) & 1) * 8;

    float c[2][4][4];
#pragma unroll
    for (int i = 0; i < 2; i++)
#pragma unroll
        for (int j = 0; j < 4; j++)
#pragma unroll
            for (int q = 0; q < 4; q++) c[i][j][q] = 0.f;

    const int NK = D_MODEL / 64;
    gemm_issue(sb, 0, 0, bm, bn, tid, D_MODEL, Ah, Al, Bh, Bl);
    for (int kc = 0; kc < NK; kc++) {
        if (kc + 1 < NK) { gemm_issue(sb, (kc + 1) & 1, kc + 1, bm, bn, tid, D_MODEL, Ah, Al, Bh, Bl); CP_WAIT1(); }
        else CP_WAIT0();
        __syncthreads();
        uint32_t uAh = sb + (uint32_t)(kc & 1) * GT_STG2;
        uint32_t uAl = uAh + GT_TILE2;
        uint32_t uBh = uAh + 2 * GT_TILE2;
        uint32_t uBl = uAh + 3 * GT_TILE2;
#pragma unroll
        for (int ks = 0; ks < 4; ks++) {
            uint32_t ah[2][4], al[2][4], bh[2][4], bl[2][4];
#pragma unroll
            for (int ma = 0; ma < 2; ma++) {
                uint32_t off = ((a_row + ma * 16) * SA + a_kc + ks * 16) * 2;
                LDSM4(ah[ma][0], ah[ma][1], ah[ma][2], ah[ma][3], uAh + off);
                LDSM4(al[ma][0], al[ma][1], al[ma][2], al[ma][3], uAl + off);
            }
#pragma unroll
            for (int nb2 = 0; nb2 < 2; nb2++) {
                uint32_t off = ((b_row + nb2 * 16) * SA + b_kc + ks * 16) * 2;
                LDSM4(bh[nb2][0], bh[nb2][1], bh[nb2][2], bh[nb2][3], uBh + off);
                LDSM4(bl[nb2][0], bl[nb2][1], bl[nb2][2], bl[nb2][3], uBl + off);
            }
#pragma unroll
            for (int ma = 0; ma < 2; ma++)
#pragma unroll
                for (int nb = 0; nb < 4; nb++) {
                    int n2 = nb >> 1, o = (nb & 1) * 2;
                    MMA16816(c[ma][nb], ah[ma], bh[n2][o], bh[n2][o + 1]);
                    MMA16816(c[ma][nb], ah[ma], bl[n2][o], bl[n2][o + 1]);
                    MMA16816(c[ma][nb], al[ma], bh[n2][o], bh[n2][o + 1]);
                }
        }
        __syncthreads();
    }

    int r0 = bm * 128 + wm * 32 + (lane >> 2);
#pragma unroll
    for (int ma = 0; ma < 2; ma++) {
#pragma unroll
        for (int nb = 0; nb < 4; nb++) {
            int col = bn * 128 + wn * 32 + nb * 8 + (lane & 3) * 2;
            int ra = r0 + ma * 16, rb = ra + 8;
            float2 o0, o1;
            o0.x = c[ma][nb][0] + bias[col];
            o0.y = c[ma][nb][1] + bias[col + 1];
            o1.x = c[ma][nb][2] + bias[col];
            o1.y = c[ma][nb][3] + bias[col + 1];
            float2 r2a = *(const float2*)&res[(size_t)ra * N + col];
            float2 r2b = *(const float2*)&res[(size_t)rb * N + col];
            o0.x += r2a.x; o0.y += r2a.y;
            o1.x += r2b.x; o1.y += r2b.y;
            *(float2*)&C[(size_t)ra * N + col] = o0;
            *(float2*)&C[(size_t)rb * N + col] = o1;
        }
    }
}

// ---------------------------------------------------------------------------
// Stats-only scores pass: per (row, 128-ktile) partial (m, sumexp). No S write.
// ---------------------------------------------------------------------------
#define SK 72
#define SCORES_SMEM (4 * 128 * SK * 2)

__global__ void __launch_bounds__(256) scores_stats(
    const bf16* __restrict__ qh, const bf16* __restrict__ ql,
    const bf16* __restrict__ kh, const bf16* __restrict__ kl,
    float2* __restrict__ part) {
    int kt = blockIdx.x, qt = blockIdx.y, bh = blockIdx.z;
    if (kt > qt) return;
    int tid = threadIdx.x;

    extern __shared__ char dyn[];
    bf16* sQh = (bf16*)dyn;
    bf16* sQl = sQh + 128 * SK;
    bf16* sKh = sQl + 128 * SK;
    bf16* sKl = sKh + 128 * SK;
    __shared__ float2 sstat[128][2];

    const bf16* qhb = qh + ((size_t)bh * T + qt * 128) * DH;
    const bf16* qlb = ql + ((size_t)bh * T + qt * 128) * DH;
    const bf16* khb = kh + ((size_t)bh * T + kt * 128) * DH;
    const bf16* klb = kl + ((size_t)bh * T + kt * 128) * DH;

#pragma unroll
    for (int it = 0; it < 4; it++) {
        int idx = tid + it * 256;
        int r = idx >> 3, cc = (idx & 7) * 8;
        int so = r * SK + cc;
        size_t go = (size_t)r * DH + cc;
        *(uint4*)&sQh[so] = *(const uint4*)&qhb[go];
        *(uint4*)&sQl[so] = *(const uint4*)&qlb[go];
        *(uint4*)&sKh[so] = *(const uint4*)&khb[go];
        *(uint4*)&sKl[so] = *(const uint4*)&klb[go];
    }
    __syncthreads();

    int wid = tid >> 5, lane = tid & 31;
    int wm = wid & 3, wn = wid >> 2;
    uint32_t uQh = smem_u32(sQh), uQl = smem_u32(sQl);
    uint32_t uKh = smem_u32(sKh), uKl = smem_u32(sKl);

    int a_row = wm * 32 + ((lane >> 3) & 1) * 8 + (lane & 7);
    int a_kc  = (lane >> 4) * 8;
    int b_row = wn * 64 + (lane >> 4) * 8 + (lane & 7);
    int b_kc  = ((lane >> 3) & 1) * 8;

    float c[2][8][4];
#pragma unroll
    for (int i = 0; i < 2; i++)
#pragma unroll
        for (int j = 0; j < 8; j++)
#pragma unroll
            for (int q = 0; q < 4; q++) c[i][j][q] = 0.f;

#pragma unroll
    for (int ks = 0; ks < 4; ks++) {
        uint32_t ah[2][4], al[2][4], bh2[4][4], bl2[4][4];
#pragma unroll
        for (int ma = 0; ma < 2; ma++) {
            uint32_t off = ((a_row + ma * 16) * SK + a_kc + ks * 16) * 2;
            LDSM4(ah[ma][0], ah[ma][1], ah[ma][2], ah[ma][3], uQh + off);
            LDSM4(al[ma][0], al[ma][1], al[ma][2], al[ma][3], uQl + off);
        }
#pragma unroll
        for (int nb2 = 0; nb2 < 4; nb2++) {
            uint32_t off = ((b_row + nb2 * 16) * SK + b_kc + ks * 16) * 2;
            LDSM4(bh2[nb2][0], bh2[nb2][1], bh2[nb2][2], bh2[nb2][3], uKh + off);
            LDSM4(bl2[nb2][0], bl2[nb2][1], bl2[nb2][2], bl2[nb2][3], uKl + off);
        }
#pragma unroll
        for (int ma = 0; ma < 2; ma++)
#pragma unroll
            for (int nb = 0; nb < 8; nb++) {
                int n2 = nb >> 1, o = (nb & 1) * 2;
                MMA16816(c[ma][nb], ah[ma], bh2[n2][o], bh2[n2][o + 1]);
                MMA16816(c[ma][nb], ah[ma], bl2[n2][o], bl2[n2][o + 1]);
                MMA16816(c[ma][nb], al[ma], bh2[n2][o], bh2[n2][o + 1]);
            }
    }

    bool diag = (qt == kt);
#pragma unroll
    for (int ma = 0; ma < 2; ma++) {
#pragma unroll
        for (int half = 0; half < 2; half++) {
            int lrow = wm * 32 + ma * 16 + half * 8 + (lane >> 2);
            float vv[8][2];
#pragma unroll
            for (int nb = 0; nb < 8; nb++) {
                int colc = wn * 64 + nb * 8 + (lane & 3) * 2;
                float v0 = c[ma][nb][half * 2 + 0] * 0.125f;
                float v1 = c[ma][nb][half * 2 + 1] * 0.125f;
                if (diag) {
                    if (colc > lrow) v0 = -1e30f;
                    if (colc + 1 > lrow) v1 = -1e30f;
                }
                vv[nb][0] = v0; vv[nb][1] = v1;
            }
            float mt = -1e30f;
#pragma unroll
            for (int nb = 0; nb < 8; nb++) {
                mt = fmaxf(mt, vv[nb][0]);
                mt = fmaxf(mt, vv[nb][1]);
            }
            float st = 0.f;
#pragma unroll
            for (int nb = 0; nb < 8; nb++) {
                st += __expf(vv[nb][0] - mt);
                st += __expf(vv[nb][1] - mt);
            }
#pragma unroll
            for (int o = 1; o < 4; o <<= 1) {
                float om = __shfl_xor_sync(~0u, mt, o);
                float os = __shfl_xor_sync(~0u, st, o);
                ms_merge(mt, st, om, os);
            }
            if ((lane & 3) == 0) sstat[lrow][wn] = make_float2(mt, st);
        }
    }
    __syncthreads();
    if (tid < 128) {
        float2 p0 = sstat[tid][0], p1 = sstat[tid][1];
        float m = p0.x, s = p0.y;
        ms_merge(m, s, p1.x, p1.y);
        part[((size_t)bh * T + qt * 128 + tid) * 16 + kt] = make_float2(m, s);
    }
}

// ---------------------------------------------------------------------------
// Reduce per-row partials -> (m, 1/sum)
// ---------------------------------------------------------------------------
__global__ void reduce_stats(const float2* __restrict__ part,
                             float* __restrict__ mA, float* __restrict__ invA) {
    int row = blockIdx.x * 256 + threadIdx.x;
    int r = row & (T - 1);
    int nkb = (r >> 7) + 1;
    float m = -1e30f, s = 0.f;
    const float2* p = part + (size_t)row * 16;
    for (int i = 0; i < nkb; i++) {
        float2 v = p[i];
        ms_merge(m, s, v.x, v.y);
    }
    mA[row] = m;
    invA[row] = 1.f / s;
}

// ---------------------------------------------------------------------------
// Fused av (R10 proven): recompute S, normalize in regs, write P, repack,
// MMA with V -> O. 256 threads, 2-stage cp.async.
// ---------------------------------------------------------------------------
#define FK 72
#define FA_QT2  (128 * FK * 2)
#define FA_KT2  (64 * FK * 2)
#define FA_STG  (4 * FA_KT2)
#define FA_KV   (2 * FA_QT2)
#define FA_SMEM (FA_KV + 2 * FA_STG)

__device__ __forceinline__ void fa_issue_kv(
    uint32_t sb, int st, int kt, int tid,
    const bf16* __restrict__ kh, const bf16* __restrict__ kl,
    const bf16* __restrict__ vh, const bf16* __restrict__ vl) {
    uint32_t base = sb + FA_KV + (uint32_t)st * FA_STG;
#pragma unroll
    for (int p = 0; p < 2; p++) {
        int idx = tid + p * 256;
        int r = idx >> 3, cc = (idx & 7) * 8;
        size_t g = (size_t)(kt * 64 + r) * DH + cc;
        uint32_t so = (uint32_t)(r * FK + cc) * 2;
        cp16(base + so, kh + g);
        cp16(base + FA_KT2 + so, kl + g);
        cp16(base + 2 * FA_KT2 + so, vh + g);
        cp16(base + 3 * FA_KT2 + so, vl + g);
    }
    CP_COMMIT();
}

__global__ void __launch_bounds__(256) av_fused(
    const bf16* __restrict__ qhA, const bf16* __restrict__ qlA,
    const bf16* __restrict__ khA, const bf16* __restrict__ klA,
    const bf16* __restrict__ vhA, const bf16* __restrict__ vlA,
    const float* __restrict__ mA, const float* __restrict__ invA,
    float* __restrict__ attn,
    bf16* __restrict__ ohi, bf16* __restrict__ olo) {
    int qt = blockIdx.x, bh = blockIdx.y;
    int b = bh >> 4, h = bh & 15;
    int tid = threadIdx.x;
    int wid = tid >> 5, lane = tid & 31;

    extern __shared__ char dyn[];
    uint32_t sb = smem_u32(dyn);

    const bf16* qh = qhA + ((size_t)bh * T + qt * 128) * DH;
    const bf16* ql = qlA + ((size_t)bh * T + qt * 128) * DH;
    const bf16* kh = khA + (size_t)bh * T * DH;
    const bf16* kl = klA + (size_t)bh * T * DH;
    const bf16* vh = vhA + (size_t)bh * T * DH;
    const bf16* vl = vlA + (size_t)bh * T * DH;
    float* sblk = attn + ((size_t)bh * T + qt * 128) * T;

    int lr0 = wid * 16 + (lane >> 2);
    int lr1 = lr0 + 8;
    int qrow0 = qt * 128 + lr0, qrow1 = qt * 128 + lr1;
    float m0 = mA[bh * T + qrow0], iv0 = invA[bh * T + qrow0];
    float m1 = mA[bh * T + qrow1], iv1 = invA[bh * T + qrow1];

    {
#pragma unroll
        for (int p = 0; p < 4; p++) {
            int idx = tid + p * 256;
            int r = idx >> 3, cc = (idx & 7) * 8;
            size_t g = (size_t)r * DH + cc;
            uint32_t so = (uint32_t)(r * FK + cc) * 2;
            cp16(sb + so, qh + g);
            cp16(sb + FA_QT2 + so, ql + g);
        }
        CP_COMMIT();
    }
    fa_issue_kv(sb, 0, 0, tid, kh, kl, vh, vl);

    int a_row = wid * 16 + ((lane >> 3) & 1) * 8 + (lane & 7);
    int a_kc  = (lane >> 4) * 8;
    int b_row8 = (lane >> 4) * 8 + (lane & 7);
    int b_kc  = ((lane >> 3) & 1) * 8;
    int v_k   = lane & 15;
    int v_n   = (lane >> 4) * 8;

    uint32_t qa_h[4][4], qa_l[4][4];
    float o[8][4];
#pragma unroll
    for (int i = 0; i < 8; i++)
#pragma unroll
        for (int q = 0; q < 4; q++) o[i][q] = 0.f;

    int nk = 2 * qt + 2;
    for (int kt = 0; kt < nk; kt++) {
        if (kt + 1 < nk) { fa_issue_kv(sb, (kt + 1) & 1, kt + 1, tid, kh, kl, vh, vl); CP_WAIT1(); }
        else CP_WAIT0();
        __syncthreads();

        if (kt == 0) {
#pragma unroll
            for (int ks = 0; ks < 4; ks++) {
                uint32_t off = (a_row * FK + a_kc + ks * 16) * 2;
                LDSM4(qa_h[ks][0], qa_h[ks][1], qa_h[ks][2], qa_h[ks][3], sb + off);
                LDSM4(qa_l[ks][0], qa_l[ks][1], qa_l[ks][2], qa_l[ks][3], sb + FA_QT2 + off);
            }
        }

        uint32_t uKh = sb + FA_KV + (uint32_t)(kt & 1) * FA_STG;
        uint32_t uKl = uKh + FA_KT2;
        uint32_t uVh = uKh + 2 * FA_KT2;
        uint32_t uVl = uKh + 3 * FA_KT2;

        float s[8][4];
#pragma unroll
        for (int i = 0; i < 8; i++)
#pragma unroll
            for (int q = 0; q < 4; q++) s[i][q] = 0.f;

#pragma unroll
        for (int ks = 0; ks < 4; ks++) {
            uint32_t kbh[4][4], kbl[4][4];
#pragma unroll
            for (int nb2 = 0; nb2 < 4; nb2++) {
                uint32_t off = ((nb2 * 16 + b_row8) * FK + b_kc + ks * 16) * 2;
                LDSM4(kbh[nb2][0], kbh[nb2][1], kbh[nb2][2], kbh[nb2][3], uKh + off);
                LDSM4(kbl[nb2][0], kbl[nb2][1], kbl[nb2][2], kbl[nb2][3], uKl + off);
            }
#pragma unroll
            for (int nb = 0; nb < 8; nb++) {
                int n2 = nb >> 1, oo = (nb & 1) * 2;
                MMA16816(s[nb], qa_h[ks], kbh[n2][oo], kbh[n2][oo + 1]);
                MMA16816(s[nb], qa_h[ks], kbl[n2][oo], kbl[n2][oo + 1]);
                MMA16816(s[nb], qa_l[ks], kbh[n2][oo], kbh[n2][oo + 1]);
            }
        }

        uint32_t pa_h[4][4], pa_l[4][4];
#pragma unroll
        for (int nb = 0; nb < 8; nb++) {
            int kcol = kt * 64 + nb * 8 + (lane & 3) * 2;
            float p0 = (kcol     <= qrow0) ? __expf(s[nb][0] * 0.125f - m0) * iv0 : 0.f;
            float p1 = (kcol + 1 <= qrow0) ? __expf(s[nb][1] * 0.125f - m0) * iv0 : 0.f;
            float p2 = (kcol     <= qrow1) ? __expf(s[nb][2] * 0.125f - m1) * iv1 : 0.f;
            float p3 = (kcol + 1 <= qrow1) ? __expf(s[nb][3] * 0.125f - m1) * iv1 : 0.f;
            float2 w0; w0.x = p0; w0.y = p1;
            float2 w1; w1.x = p2; w1.y = p3;
            *(float2*)&sblk[(size_t)lr0 * T + kcol] = w0;
            *(float2*)&sblk[(size_t)lr1 * T + kcol] = w1;
            bf16 h0 = __float2bfloat16(p0), h1b = __float2bfloat16(p1);
            bf16 h2 = __float2bfloat16(p2), h3 = __float2bfloat16(p3);
            float l0f = p0 - __bfloat162float(h0), l1f = p1 - __bfloat162float(h1b);
            float l2f = p2 - __bfloat162float(h2), l3f = p3 - __bfloat162float(h3);
            int j = nb >> 1, hf = (nb & 1) * 2;
            bf162 t0; t0.x = h0; t0.y = h1b;
            bf162 t1; t1.x = h2; t1.y = h3;
            pa_h[j][hf]     = *(uint32_t*)&t0;
            pa_h[j][hf + 1] = *(uint32_t*)&t1;
            pa_l[j][hf]     = packbf(l0f, l1f);
            pa_l[j][hf + 1] = packbf(l2f, l3f);
        }

#pragma unroll
        for (int j = 0; j < 4; j++) {
            uint32_t vbh[4][4], vbl[4][4];
#pragma unroll
            for (int ns = 0; ns < 4; ns++) {
                uint32_t off = ((j * 16 + v_k) * FK + ns * 16 + v_n) * 2;
                LDSM4T(vbh[ns][0], vbh[ns][1], vbh[ns][2], vbh[ns][3], uVh + off);
                LDSM4T(vbl[ns][0], vbl[ns][1], vbl[ns][2], vbl[ns][3], uVl + off);
            }
#pragma unroll
            for (int nb = 0; nb < 8; nb++) {
                int n2 = nb >> 1, oo = (nb & 1) * 2;
                MMA16816(o[nb], pa_h[j], vbh[n2][oo], vbh[n2][oo + 1]);
                MMA16816(o[nb], pa_h[j], vbl[n2][oo], vbl[n2][oo + 1]);
                MMA16816(o[nb], pa_l[j], vbh[n2][oo], vbh[n2][oo + 1]);
            }
        }
        __syncthreads();
    }

    {
        int c0u = (qt + 1) * 128;
        int r = tid >> 1, hf = tid & 1;
        float4 z = make_float4(0.f, 0.f, 0.f, 0.f);
        for (int cc = c0u + hf * 4; cc < T; cc += 8)
            *(float4*)&sblk[(size_t)r * T + cc] = z;
    }

#pragma unroll
    for (int nb = 0; nb < 8; nb++) {
        int d = nb * 8 + (lane & 3) * 2;
        size_t i0 = ((size_t)(b * T + qrow0)) * D_MODEL + h * DH + d;
        size_t i1 = ((size_t)(b * T + qrow1)) * D_MODEL + h * DH + d;
        float y0 = o[nb][0], y1 = o[nb][1], y2 = o[nb][2], y3 = o[nb][3];
        bf16 h0 = __float2bfloat16(y0), h1b = __float2bfloat16(y1);
        bf16 h2 = __float2bfloat16(y2), h3 = __float2bfloat16(y3);
        bf162 hv0; hv0.x = h0; hv0.y = h1b;
        bf162 hv1; hv1.x = h2; hv1.y = h3;
        *(bf162*)&ohi[i0] = hv0;
        *(bf162*)&ohi[i1] = hv1;
        bf162 lv0, lv1;
        lv0.x = __float2bfloat16(y0 - __bfloat162float(h0));
        lv0.y = __float2bfloat16(y1 - __bfloat162float(h1b));
        lv1.x = __float2bfloat16(y2 - __bfloat162float(h2));
        lv1.y = __float2bfloat16(y3 - __bfloat162float(h3));
        *(bf162*)&olo[i0] = lv0;
        *(bf162*)&olo[i1] = lv1;
    }
}

// ---------------------------------------------------------------------------
extern "C" void kernel_launch(void* const* d_in, const int* in_sizes, int n_in,
                              void* d_out, int out_size) {
    (void)in_sizes; (void)n_in; (void)out_size;
    const float* x     = (const float*)d_in[0];
    const float* ln_g  = (const float*)d_in[1];
    const float* ln_b  = (const float*)d_in[2];
    const float* qkv_w = (const float*)d_in[3];
    const float* qkv_b = (const float*)d_in[4];
    const float* out_w = (const float*)d_in[5];
    const float* out_b = (const float*)d_in[6];

    float* xout = (float*)d_out;
    float* attn = xout + (size_t)BT * D_MODEL;

    static bf16 *p_hhi = nullptr, *p_hlo, *p_wqh, *p_wql, *p_woh, *p_wol;
    static bf16 *p_qh, *p_ql, *p_kh, *p_kl, *p_vh, *p_vl, *p_aoh, *p_aol;
    static float2* p_part;
    static float *p_m, *p_inv;
    if (!p_hhi) {
        cudaGetSymbolAddress((void**)&p_hhi, g_h_hi);
        cudaGetSymbolAddress((void**)&p_hlo, g_h_lo);
        cudaGetSymbolAddress((void**)&p_wqh, g_wq_hi);
        cudaGetSymbolAddress((void**)&p_wql, g_wq_lo);
        cudaGetSymbolAddress((void**)&p_woh, g_wo_hi);
        cudaGetSymbolAddress((void**)&p_wol, g_wo_lo);
        cudaGetSymbolAddress((void**)&p_qh, g_q_hi);
        cudaGetSymbolAddress((void**)&p_ql, g_q_lo);
        cudaGetSymbolAddress((void**)&p_kh, g_k_hi);
        cudaGetSymbolAddress((void**)&p_kl, g_k_lo);
        cudaGetSymbolAddress((void**)&p_vh, g_v_hi);
        cudaGetSymbolAddress((void**)&p_vl, g_v_lo);
        cudaGetSymbolAddress((void**)&p_aoh, g_ao_hi);
        cudaGetSymbolAddress((void**)&p_aol, g_ao_lo);
        cudaGetSymbolAddress((void**)&p_part, g_part);
        cudaGetSymbolAddress((void**)&p_m, g_m);
        cudaGetSymbolAddress((void**)&p_inv, g_inv);
        cudaFuncSetAttribute(gemm_mma_qkv, cudaFuncAttributeMaxDynamicSharedMemorySize, QKV_SMEM);
        cudaFuncSetAttribute(gemm_mma_out, cudaFuncAttributeMaxDynamicSharedMemorySize, GEMM_SMEM);
        cudaFuncSetAttribute(scores_stats, cudaFuncAttributeMaxDynamicSharedMemorySize, SCORES_SMEM);
        cudaFuncSetAttribute(av_fused, cudaFuncAttributeMaxDynamicSharedMemorySize, FA_SMEM);
    }

    ln_kernel<<<BT, 256>>>(x, ln_g, ln_b, p_hhi, p_hlo);
    tsplit_kernel<<<dim3(QKV_N / 32, D_MODEL / 32), dim3(32, 8)>>>(qkv_w, p_wqh, p_wql, D_MODEL, QKV_N);
    tsplit_kernel<<<dim3(D_MODEL / 32, D_MODEL / 32), dim3(32, 8)>>>(out_w, p_woh, p_wol, D_MODEL, D_MODEL);

    gemm_mma_qkv<<<dim3(QKV_N / 192, BT / 128), 768, QKV_SMEM>>>(
        p_hhi, p_hlo, p_wqh, p_wql, qkv_b, p_qh, p_ql, p_kh, p_kl, p_vh, p_vl);

    scores_stats<<<dim3(16, 16, 32), 256, SCORES_SMEM>>>(p_qh, p_ql, p_kh, p_kl, p_part);
    reduce_stats<<<(32 * T) / 256, 256>>>(p_part, p_m, p_inv);
    av_fused<<<dim3(16, 32), 256, FA_SMEM>>>(p_qh, p_ql, p_kh, p_kl, p_vh, p_vl,
                                             p_m, p_inv, attn, p_aoh, p_aol);

    gemm_mma_out<<<dim3(D_MODEL / 128, BT / 128), 512, GEMM_SMEM>>>(
        p_aoh, p_aol, p_woh, p_wol, out_b, x, xout);
}

// round 16
// speedup vs baseline: 1.6022x; 1.0296x over previous
#include <cuda_runtime.h>
#include <cuda_bf16.h>
#include <cstdint>
#include <math.h>

#define D_MODEL 1024
#define NH      16
#define DH      64
#define BATCH   2
#define T       2048
#define BT      4096
#define QKV_N   3072

typedef __nv_bfloat16 bf16;
typedef __nv_bfloat162 bf162;

// ---------------------------------------------------------------------------
// Scratch
// ---------------------------------------------------------------------------
__device__ bf16 g_h_hi[(size_t)BT * D_MODEL];
__device__ bf16 g_h_lo[(size_t)BT * D_MODEL];
__device__ bf16 g_wq_hi[(size_t)QKV_N * D_MODEL];
__device__ bf16 g_wq_lo[(size_t)QKV_N * D_MODEL];
__device__ bf16 g_wo_hi[(size_t)D_MODEL * D_MODEL];
__device__ bf16 g_wo_lo[(size_t)D_MODEL * D_MODEL];
__device__ bf16 g_q_hi[(size_t)32 * T * DH];
__device__ bf16 g_q_lo[(size_t)32 * T * DH];
__device__ bf16 g_k_hi[(size_t)32 * T * DH];
__device__ bf16 g_k_lo[(size_t)32 * T * DH];
__device__ bf16 g_v_hi[(size_t)32 * T * DH];
__device__ bf16 g_v_lo[(size_t)32 * T * DH];
__device__ bf16 g_ao_hi[(size_t)BT * D_MODEL];
__device__ bf16 g_ao_lo[(size_t)BT * D_MODEL];
__device__ float2 g_part[(size_t)32 * T * 16];
__device__ float  g_m[(size_t)32 * T];
__device__ float  g_inv[(size_t)32 * T];

// ---------------------------------------------------------------------------
// Helpers
// ---------------------------------------------------------------------------
__device__ __forceinline__ uint32_t smem_u32(const void* p) {
    uint32_t a;
    asm("{ .reg .u64 t; cvta.to.shared.u64 t, %1; cvt.u32.u64 %0, t; }" : "=r"(a) : "l"(p));
    return a;
}
__device__ __forceinline__ void cp16(uint32_t dst, const void* src) {
    asm volatile("cp.async.cg.shared.global [%0], [%1], 16;" :: "r"(dst), "l"(src));
}
#define CP_COMMIT() asm volatile("cp.async.commit_group;" ::: "memory")
#define CP_WAIT0()  asm volatile("cp.async.wait_group 0;" ::: "memory")
#define CP_WAIT1()  asm volatile("cp.async.wait_group 1;" ::: "memory")
#define LDSM4(r0, r1, r2, r3, addr)                                              \
    asm volatile("ldmatrix.sync.aligned.m8n8.x4.shared.b16 {%0,%1,%2,%3}, [%4];" \
                 : "=r"(r0), "=r"(r1), "=r"(r2), "=r"(r3) : "r"(addr))
#define LDSM4T(r0, r1, r2, r3, addr)                                                   \
    asm volatile("ldmatrix.sync.aligned.m8n8.x4.trans.shared.b16 {%0,%1,%2,%3}, [%4];" \
                 : "=r"(r0), "=r"(r1), "=r"(r2), "=r"(r3) : "r"(addr))
#define MMA16816(c, a, b0, b1)                                                   \
    asm volatile("mma.sync.aligned.m16n8k16.row.col.f32.bf16.bf16.f32 "          \
                 "{%0,%1,%2,%3}, {%4,%5,%6,%7}, {%8,%9}, {%0,%1,%2,%3};"         \
                 : "+f"((c)[0]), "+f"((c)[1]), "+f"((c)[2]), "+f"((c)[3])        \
                 : "r"((a)[0]), "r"((a)[1]), "r"((a)[2]), "r"((a)[3]),           \
                   "r"(b0), "r"(b1))

__device__ __forceinline__ void ms_merge(float& m, float& s, float om, float os) {
    float M = fmaxf(m, om);
    s = s * __expf(m - M) + os * __expf(om - M);
    m = M;
}
__device__ __forceinline__ uint32_t packbf(float a, float b) {
    bf162 v; v.x = __float2bfloat16(a); v.y = __float2bfloat16(b);
    return *(uint32_t*)&v;
}

// ---------------------------------------------------------------------------
// LayerNorm -> bf16 hi/lo split
// ---------------------------------------------------------------------------
__global__ void ln_kernel(const float* __restrict__ x, const float* __restrict__ gam,
                          const float* __restrict__ bet,
                          bf16* __restrict__ ohi, bf16* __restrict__ olo) {
    int row = blockIdx.x;
    const float* xr = x + (size_t)row * D_MODEL;
    float v[4];
    float s = 0.f, s2 = 0.f;
#pragma unroll
    for (int i = 0; i < 4; i++) {
        v[i] = xr[threadIdx.x + i * 256];
        s += v[i]; s2 += v[i] * v[i];
    }
#pragma unroll
    for (int o = 16; o > 0; o >>= 1) {
        s  += __shfl_xor_sync(~0u, s, o);
        s2 += __shfl_xor_sync(~0u, s2, o);
    }
    __shared__ float rs[8], rs2[8];
    int wid = threadIdx.x >> 5, lid = threadIdx.x & 31;
    if (lid == 0) { rs[wid] = s; rs2[wid] = s2; }
    __syncthreads();
    s = 0.f; s2 = 0.f;
#pragma unroll
    for (int i = 0; i < 8; i++) { s += rs[i]; s2 += rs2[i]; }
    float mu  = s * (1.f / D_MODEL);
    float var = s2 * (1.f / D_MODEL) - mu * mu;
    float inv = rsqrtf(var + 1e-5f);
#pragma unroll
    for (int i = 0; i < 4; i++) {
        int c = threadIdx.x + i * 256;
        float y = (v[i] - mu) * inv * gam[c] + bet[c];
        bf16 h = __float2bfloat16(y);
        ohi[(size_t)row * D_MODEL + c] = h;
        olo[(size_t)row * D_MODEL + c] = __float2bfloat16(y - __bfloat162float(h));
    }
}

// ---------------------------------------------------------------------------
// Transpose + bf16 split: W[K][N] -> out[N][K]
// ---------------------------------------------------------------------------
__global__ void tsplit_kernel(const float* __restrict__ W,
                              bf16* __restrict__ hi, bf16* __restrict__ lo,
                              int K, int N) {
    __shared__ float t[32][33];
    int n0 = blockIdx.x * 32, k0 = blockIdx.y * 32;
    int tx = threadIdx.x, ty = threadIdx.y;
#pragma unroll
    for (int j = 0; j < 4; j++)
        t[ty + j * 8][tx] = W[(size_t)(k0 + ty + j * 8) * N + n0 + tx];
    __syncthreads();
#pragma unroll
    for (int j = 0; j < 4; j++) {
        float v = t[tx][ty + j * 8];
        size_t o = (size_t)(n0 + ty + j * 8) * K + k0 + tx;
        bf16 h = __float2bfloat16(v);
        hi[o] = h;
        lo[o] = __float2bfloat16(v - __bfloat162float(h));
    }
}

// ---------------------------------------------------------------------------
// Dense GEMMs: 512 thr, block 256x128x64, warp grid 4(M)x4(N), warp tile 64x32.
// 2-stage cp.async. A = 256 rows, B = 128 rows.
// ---------------------------------------------------------------------------
#define SA 72
#define GA_T   (256 * SA * 2)             // 36864 (one A tile: hi or lo)
#define GB_T   (128 * SA * 2)             // 18432
#define G_STG  (2 * GA_T + 2 * GB_T)      // 110592
#define G_SMEM (2 * G_STG)                // 221184

__device__ __forceinline__ void g2_issue(
    uint32_t sb, int st, int kc, int bm, int bn, int tid, int K,
    const bf16* __restrict__ Ah, const bf16* __restrict__ Al,
    const bf16* __restrict__ Bh, const bf16* __restrict__ Bl) {
    int c0 = kc * 64;
    uint32_t base = sb + (uint32_t)st * G_STG;
    // A: 256 rows x 64 cols = 2048 cp16 slots
#pragma unroll
    for (int it = 0; it < 4; it++) {
        int idx = tid + it * 512;
        int r = idx >> 3, cc = (idx & 7) * 8;
        size_t ga = (size_t)(bm * 256 + r) * K + c0 + cc;
        uint32_t so = (uint32_t)(r * SA + cc) * 2;
        cp16(base + so, Ah + ga);
        cp16(base + GA_T + so, Al + ga);
    }
    // B: 128 rows x 64 cols = 1024 cp16 slots
#pragma unroll
    for (int it = 0; it < 2; it++) {
        int idx = tid + it * 512;
        int r = idx >> 3, cc = (idx & 7) * 8;
        size_t gb = (size_t)(bn * 128 + r) * K + c0 + cc;
        uint32_t so = (uint32_t)(r * SA + cc) * 2;
        cp16(base + 2 * GA_T + so, Bh + gb);
        cp16(base + 2 * GA_T + GB_T + so, Bl + gb);
    }
    CP_COMMIT();
}

#define G2_MAINLOOP(K_)                                                          \
    int a_row = wm * 64 + ((lane >> 3) & 1) * 8 + (lane & 7);                    \
    int a_kc  = (lane >> 4) * 8;                                                 \
    int b_row = wn * 32 + (lane >> 4) * 8 + (lane & 7);                          \
    int b_kc  = ((lane >> 3) & 1) * 8;                                           \
    float c[4][4][4];                                                            \
    _Pragma("unroll") for (int i = 0; i < 4; i++)                                \
    _Pragma("unroll") for (int j = 0; j < 4; j++)                                \
    _Pragma("unroll") for (int q = 0; q < 4; q++) c[i][j][q] = 0.f;              \
    const int NK = (K_) / 64;                                                    \
    g2_issue(sb, 0, 0, bm, bn, tid, (K_), Ah, Al, Bh, Bl);                       \
    for (int kc = 0; kc < NK; kc++) {                                            \
        if (kc + 1 < NK) { g2_issue(sb, (kc + 1) & 1, kc + 1, bm, bn, tid,       \
                                    (K_), Ah, Al, Bh, Bl); CP_WAIT1(); }         \
        else CP_WAIT0();                                                         \
        __syncthreads();                                                         \
        uint32_t uAh = sb + (uint32_t)(kc & 1) * G_STG;                          \
        uint32_t uAl = uAh + GA_T;                                               \
        uint32_t uBh = uAh + 2 * GA_T;                                           \
        uint32_t uBl = uBh + GB_T;                                               \
        _Pragma("unroll")                                                        \
        for (int ks = 0; ks < 4; ks++) {                                         \
            uint32_t bh[2][4], bl[2][4];                                         \
            _Pragma("unroll")                                                    \
            for (int nb2 = 0; nb2 < 2; nb2++) {                                  \
                uint32_t off = ((b_row + nb2 * 16) * SA + b_kc + ks * 16) * 2;   \
                LDSM4(bh[nb2][0], bh[nb2][1], bh[nb2][2], bh[nb2][3], uBh + off);\
                LDSM4(bl[nb2][0], bl[nb2][1], bl[nb2][2], bl[nb2][3], uBl + off);\
            }                                                                    \
            _Pragma("unroll")                                                    \
            for (int ma = 0; ma < 4; ma++) {                                     \
                uint32_t ah[4], al[4];                                           \
                uint32_t off = ((a_row + ma * 16) * SA + a_kc + ks * 16) * 2;    \
                LDSM4(ah[0], ah[1], ah[2], ah[3], uAh + off);                    \
                LDSM4(al[0], al[1], al[2], al[3], uAl + off);                    \
                _Pragma("unroll")                                                \
                for (int nb = 0; nb < 4; nb++) {                                 \
                    int n2 = nb >> 1, o = (nb & 1) * 2;                          \
                    MMA16816(c[ma][nb], ah, bh[n2][o], bh[n2][o + 1]);           \
                    MMA16816(c[ma][nb], ah, bl[n2][o], bl[n2][o + 1]);           \
                    MMA16816(c[ma][nb], al, bh[n2][o], bh[n2][o + 1]);           \
                }                                                                \
            }                                                                    \
        }                                                                        \
        __syncthreads();                                                         \
    }

__global__ void __launch_bounds__(512) gemm_mma_qkv(
    const bf16* __restrict__ Ah, const bf16* __restrict__ Al,
    const bf16* __restrict__ Bh, const bf16* __restrict__ Bl,
    const float* __restrict__ bias,
    bf16* __restrict__ qhi, bf16* __restrict__ qlo,
    bf16* __restrict__ khi, bf16* __restrict__ klo,
    bf16* __restrict__ vhi, bf16* __restrict__ vlo) {
    extern __shared__ char dyn[];
    uint32_t sb = smem_u32(dyn);
    int tid = threadIdx.x;
    int wid = tid >> 5, lane = tid & 31;
    int wm = wid & 3, wn = wid >> 2;
    int bm = blockIdx.y, bn = blockIdx.x;

    G2_MAINLOOP(D_MODEL)

    int r0 = bm * 256 + wm * 64 + (lane >> 2);
#pragma unroll
    for (int ma = 0; ma < 4; ma++) {
#pragma unroll
        for (int nb = 0; nb < 4; nb++) {
            int col = bn * 128 + wn * 32 + nb * 8 + (lane & 3) * 2;
            int hg = col >> 6;
            int sec = hg >> 4;
            int h = hg & 15;
            int c64 = col & 63;
            bf16* dh = (sec == 0) ? qhi : (sec == 1) ? khi : vhi;
            bf16* dl = (sec == 0) ? qlo : (sec == 1) ? klo : vlo;
            float bx = bias[col], by = bias[col + 1];
#pragma unroll
            for (int half = 0; half < 2; half++) {
                int row = r0 + ma * 16 + half * 8;
                int t = row & (T - 1), b = row >> 11;
                size_t idx = (((size_t)(b * NH + h)) * T + t) * DH + c64;
                float y0 = c[ma][nb][half * 2 + 0] + bx;
                float y1 = c[ma][nb][half * 2 + 1] + by;
                bf16 h0 = __float2bfloat16(y0);
                bf16 h1 = __float2bfloat16(y1);
                bf162 hv; hv.x = h0; hv.y = h1;
                bf162 lv;
                lv.x = __float2bfloat16(y0 - __bfloat162float(h0));
                lv.y = __float2bfloat16(y1 - __bfloat162float(h1));
                *(bf162*)&dh[idx] = hv;
                *(bf162*)&dl[idx] = lv;
            }
        }
    }
}

__global__ void __launch_bounds__(512) gemm_mma_out(
    const bf16* __restrict__ Ah, const bf16* __restrict__ Al,
    const bf16* __restrict__ Bh, const bf16* __restrict__ Bl,
    const float* __restrict__ bias, const float* __restrict__ res,
    float* __restrict__ C) {
    const int N = D_MODEL;
    extern __shared__ char dyn[];
    uint32_t sb = smem_u32(dyn);
    int tid = threadIdx.x;
    int wid = tid >> 5, lane = tid & 31;
    int wm = wid & 3, wn = wid >> 2;
    int bm = blockIdx.y, bn = blockIdx.x;

    G2_MAINLOOP(D_MODEL)

    int r0 = bm * 256 + wm * 64 + (lane >> 2);
#pragma unroll
    for (int ma = 0; ma < 4; ma++) {
#pragma unroll
        for (int nb = 0; nb < 4; nb++) {
            int col = bn * 128 + wn * 32 + nb * 8 + (lane & 3) * 2;
            int ra = r0 + ma * 16, rb = ra + 8;
            float2 o0, o1;
            o0.x = c[ma][nb][0] + bias[col];
            o0.y = c[ma][nb][1] + bias[col + 1];
            o1.x = c[ma][nb][2] + bias[col];
            o1.y = c[ma][nb][3] + bias[col + 1];
            float2 r2a = *(const float2*)&res[(size_t)ra * N + col];
            float2 r2b = *(const float2*)&res[(size_t)rb * N + col];
            o0.x += r2a.x; o0.y += r2a.y;
            o1.x += r2b.x; o1.y += r2b.y;
            *(float2*)&C[(size_t)ra * N + col] = o0;
            *(float2*)&C[(size_t)rb * N + col] = o1;
        }
    }
}

// ---------------------------------------------------------------------------
// Stats-only scores pass (unchanged, proven)
// ---------------------------------------------------------------------------
#define SK 72
#define SCORES_SMEM (4 * 128 * SK * 2)

__global__ void __launch_bounds__(256) scores_stats(
    const bf16* __restrict__ qh, const bf16* __restrict__ ql,
    const bf16* __restrict__ kh, const bf16* __restrict__ kl,
    float2* __restrict__ part) {
    int kt = blockIdx.x, qt = blockIdx.y, bh = blockIdx.z;
    if (kt > qt) return;
    int tid = threadIdx.x;

    extern __shared__ char dyn[];
    bf16* sQh = (bf16*)dyn;
    bf16* sQl = sQh + 128 * SK;
    bf16* sKh = sQl + 128 * SK;
    bf16* sKl = sKh + 128 * SK;
    __shared__ float2 sstat[128][2];

    const bf16* qhb = qh + ((size_t)bh * T + qt * 128) * DH;
    const bf16* qlb = ql + ((size_t)bh * T + qt * 128) * DH;
    const bf16* khb = kh + ((size_t)bh * T + kt * 128) * DH;
    const bf16* klb = kl + ((size_t)bh * T + kt * 128) * DH;

#pragma unroll
    for (int it = 0; it < 4; it++) {
        int idx = tid + it * 256;
        int r = idx >> 3, cc = (idx & 7) * 8;
        int so = r * SK + cc;
        size_t go = (size_t)r * DH + cc;
        *(uint4*)&sQh[so] = *(const uint4*)&qhb[go];
        *(uint4*)&sQl[so] = *(const uint4*)&qlb[go];
        *(uint4*)&sKh[so] = *(const uint4*)&khb[go];
        *(uint4*)&sKl[so] = *(const uint4*)&klb[go];
    }
    __syncthreads();

    int wid = tid >> 5, lane = tid & 31;
    int wm = wid & 3, wn = wid >> 2;
    uint32_t uQh = smem_u32(sQh), uQl = smem_u32(sQl);
    uint32_t uKh = smem_u32(sKh), uKl = smem_u32(sKl);

    int a_row = wm * 32 + ((lane >> 3) & 1) * 8 + (lane & 7);
    int a_kc  = (lane >> 4) * 8;
    int b_row = wn * 64 + (lane >> 4) * 8 + (lane & 7);
    int b_kc  = ((lane >> 3) & 1) * 8;

    float c[2][8][4];
#pragma unroll
    for (int i = 0; i < 2; i++)
#pragma unroll
        for (int j = 0; j < 8; j++)
#pragma unroll
            for (int q = 0; q < 4; q++) c[i][j][q] = 0.f;

#pragma unroll
    for (int ks = 0; ks < 4; ks++) {
        uint32_t ah[2][4], al[2][4], bh2[4][4], bl2[4][4];
#pragma unroll
        for (int ma = 0; ma < 2; ma++) {
            uint32_t off = ((a_row + ma * 16) * SK + a_kc + ks * 16) * 2;
            LDSM4(ah[ma][0], ah[ma][1], ah[ma][2], ah[ma][3], uQh + off);
            LDSM4(al[ma][0], al[ma][1], al[ma][2], al[ma][3], uQl + off);
        }
#pragma unroll
        for (int nb2 = 0; nb2 < 4; nb2++) {
            uint32_t off = ((b_row + nb2 * 16) * SK + b_kc + ks * 16) * 2;
            LDSM4(bh2[nb2][0], bh2[nb2][1], bh2[nb2][2], bh2[nb2][3], uKh + off);
            LDSM4(bl2[nb2][0], bl2[nb2][1], bl2[nb2][2], bl2[nb2][3], uKl + off);
        }
#pragma unroll
        for (int ma = 0; ma < 2; ma++)
#pragma unroll
            for (int nb = 0; nb < 8; nb++) {
                int n2 = nb >> 1, o = (nb & 1) * 2;
                MMA16816(c[ma][nb], ah[ma], bh2[n2][o], bh2[n2][o + 1]);
                MMA16816(c[ma][nb], ah[ma], bl2[n2][o], bl2[n2][o + 1]);
                MMA16816(c[ma][nb], al[ma], bh2[n2][o], bh2[n2][o + 1]);
            }
    }

    bool diag = (qt == kt);
#pragma unroll
    for (int ma = 0; ma < 2; ma++) {
#pragma unroll
        for (int half = 0; half < 2; half++) {
            int lrow = wm * 32 + ma * 16 + half * 8 + (lane >> 2);
            float vv[8][2];
#pragma unroll
            for (int nb = 0; nb < 8; nb++) {
                int colc = wn * 64 + nb * 8 + (lane & 3) * 2;
                float v0 = c[ma][nb][half * 2 + 0] * 0.125f;
                float v1 = c[ma][nb][half * 2 + 1] * 0.125f;
                if (diag) {
                    if (colc > lrow) v0 = -1e30f;
                    if (colc + 1 > lrow) v1 = -1e30f;
                }
                vv[nb][0] = v0; vv[nb][1] = v1;
            }
            float mt = -1e30f;
#pragma unroll
            for (int nb = 0; nb < 8; nb++) {
                mt = fmaxf(mt, vv[nb][0]);
                mt = fmaxf(mt, vv[nb][1]);
            }
            float st = 0.f;
#pragma unroll
            for (int nb = 0; nb < 8; nb++) {
                st += __expf(vv[nb][0] - mt);
                st += __expf(vv[nb][1] - mt);
            }
#pragma unroll
            for (int o = 1; o < 4; o <<= 1) {
                float om = __shfl_xor_sync(~0u, mt, o);
                float os = __shfl_xor_sync(~0u, st, o);
                ms_merge(mt, st, om, os);
            }
            if ((lane & 3) == 0) sstat[lrow][wn] = make_float2(mt, st);
        }
    }
    __syncthreads();
    if (tid < 128) {
        float2 p0 = sstat[tid][0], p1 = sstat[tid][1];
        float m = p0.x, s = p0.y;
        ms_merge(m, s, p1.x, p1.y);
        part[((size_t)bh * T + qt * 128 + tid) * 16 + kt] = make_float2(m, s);
    }
}

// ---------------------------------------------------------------------------
// Reduce per-row partials -> (m, 1/sum)
// ---------------------------------------------------------------------------
__global__ void reduce_stats(const float2* __restrict__ part,
                             float* __restrict__ mA, float* __restrict__ invA) {
    int row = blockIdx.x * 256 + threadIdx.x;
    int r = row & (T - 1);
    int nkb = (r >> 7) + 1;
    float m = -1e30f, s = 0.f;
    const float2* p = part + (size_t)row * 16;
    for (int i = 0; i < nkb; i++) {
        float2 v = p[i];
        ms_merge(m, s, v.x, v.y);
    }
    mA[row] = m;
    invA[row] = 1.f / s;
}

// ---------------------------------------------------------------------------
// Fused av (unchanged, proven)
// ---------------------------------------------------------------------------
#define FK 72
#define FA_QT2  (128 * FK * 2)
#define FA_KT2  (64 * FK * 2)
#define FA_STG  (4 * FA_KT2)
#define FA_KV   (2 * FA_QT2)
#define FA_SMEM (FA_KV + 2 * FA_STG)

__device__ __forceinline__ void fa_issue_kv(
    uint32_t sb, int st, int kt, int tid,
    const bf16* __restrict__ kh, const bf16* __restrict__ kl,
    const bf16* __restrict__ vh, const bf16* __restrict__ vl) {
    uint32_t base = sb + FA_KV + (uint32_t)st * FA_STG;
#pragma unroll
    for (int p = 0; p < 2; p++) {
        int idx = tid + p * 256;
        int r = idx >> 3, cc = (idx & 7) * 8;
        size_t g = (size_t)(kt * 64 + r) * DH + cc;
        uint32_t so = (uint32_t)(r * FK + cc) * 2;
        cp16(base + so, kh + g);
        cp16(base + FA_KT2 + so, kl + g);
        cp16(base + 2 * FA_KT2 + so, vh + g);
        cp16(base + 3 * FA_KT2 + so, vl + g);
    }
    CP_COMMIT();
}

__global__ void __launch_bounds__(256) av_fused(
    const bf16* __restrict__ qhA, const bf16* __restrict__ qlA,
    const bf16* __restrict__ khA, const bf16* __restrict__ klA,
    const bf16* __restrict__ vhA, const bf16* __restrict__ vlA,
    const float* __restrict__ mA, const float* __restrict__ invA,
    float* __restrict__ attn,
    bf16* __restrict__ ohi, bf16* __restrict__ olo) {
    int qt = blockIdx.x, bh = blockIdx.y;
    int b = bh >> 4, h = bh & 15;
    int tid = threadIdx.x;
    int wid = tid >> 5, lane = tid & 31;

    extern __shared__ char dyn[];
    uint32_t sb = smem_u32(dyn);

    const bf16* qh = qhA + ((size_t)bh * T + qt * 128) * DH;
    const bf16* ql = qlA + ((size_t)bh * T + qt * 128) * DH;
    const bf16* kh = khA + (size_t)bh * T * DH;
    const bf16* kl = klA + (size_t)bh * T * DH;
    const bf16* vh = vhA + (size_t)bh * T * DH;
    const bf16* vl = vlA + (size_t)bh * T * DH;
    float* sblk = attn + ((size_t)bh * T + qt * 128) * T;

    int lr0 = wid * 16 + (lane >> 2);
    int lr1 = lr0 + 8;
    int qrow0 = qt * 128 + lr0, qrow1 = qt * 128 + lr1;
    float m0 = mA[bh * T + qrow0], iv0 = invA[bh * T + qrow0];
    float m1 = mA[bh * T + qrow1], iv1 = invA[bh * T + qrow1];

    {
#pragma unroll
        for (int p = 0; p < 4; p++) {
            int idx = tid + p * 256;
            int r = idx >> 3, cc = (idx & 7) * 8;
            size_t g = (size_t)r * DH + cc;
            uint32_t so = (uint32_t)(r * FK + cc) * 2;
            cp16(sb + so, qh + g);
            cp16(sb + FA_QT2 + so, ql + g);
        }
        CP_COMMIT();
    }
    fa_issue_kv(sb, 0, 0, tid, kh, kl, vh, vl);

    int a_row = wid * 16 + ((lane >> 3) & 1) * 8 + (lane & 7);
    int a_kc  = (lane >> 4) * 8;
    int b_row8 = (lane >> 4) * 8 + (lane & 7);
    int b_kc  = ((lane >> 3) & 1) * 8;
    int v_k   = lane & 15;
    int v_n   = (lane >> 4) * 8;

    uint32_t qa_h[4][4], qa_l[4][4];
    float o[8][4];
#pragma unroll
    for (int i = 0; i < 8; i++)
#pragma unroll
        for (int q = 0; q < 4; q++) o[i][q] = 0.f;

    int nk = 2 * qt + 2;
    for (int kt = 0; kt < nk; kt++) {
        if (kt + 1 < nk) { fa_issue_kv(sb, (kt + 1) & 1, kt + 1, tid, kh, kl, vh, vl); CP_WAIT1(); }
        else CP_WAIT0();
        __syncthreads();

        if (kt == 0) {
#pragma unroll
            for (int ks = 0; ks < 4; ks++) {
                uint32_t off = (a_row * FK + a_kc + ks * 16) * 2;
                LDSM4(qa_h[ks][0], qa_h[ks][1], qa_h[ks][2], qa_h[ks][3], sb + off);
                LDSM4(qa_l[ks][0], qa_l[ks][1], qa_l[ks][2], qa_l[ks][3], sb + FA_QT2 + off);
            }
        }

        uint32_t uKh = sb + FA_KV + (uint32_t)(kt & 1) * FA_STG;
        uint32_t uKl = uKh + FA_KT2;
        uint32_t uVh = uKh + 2 * FA_KT2;
        uint32_t uVl = uKh + 3 * FA_KT2;

        float s[8][4];
#pragma unroll
        for (int i = 0; i < 8; i++)
#pragma unroll
            for (int q = 0; q < 4; q++) s[i][q] = 0.f;

#pragma unroll
        for (int ks = 0; ks < 4; ks++) {
            uint32_t kbh[4][4], kbl[4][4];
#pragma unroll
            for (int nb2 = 0; nb2 < 4; nb2++) {
                uint32_t off = ((nb2 * 16 + b_row8) * FK + b_kc + ks * 16) * 2;
                LDSM4(kbh[nb2][0], kbh[nb2][1], kbh[nb2][2], kbh[nb2][3], uKh + off);
                LDSM4(kbl[nb2][0], kbl[nb2][1], kbl[nb2][2], kbl[nb2][3], uKl + off);
            }
#pragma unroll
            for (int nb = 0; nb < 8; nb++) {
                int n2 = nb >> 1, oo = (nb & 1) * 2;
                MMA16816(s[nb], qa_h[ks], kbh[n2][oo], kbh[n2][oo + 1]);
                MMA16816(s[nb], qa_h[ks], kbl[n2][oo], kbl[n2][oo + 1]);
                MMA16816(s[nb], qa_l[ks], kbh[n2][oo], kbh[n2][oo + 1]);
            }
        }

        uint32_t pa_h[4][4], pa_l[4][4];
#pragma unroll
        for (int nb = 0; nb < 8; nb++) {
            int kcol = kt * 64 + nb * 8 + (lane & 3) * 2;
            float p0 = (kcol     <= qrow0) ? __expf(s[nb][0] * 0.125f - m0) * iv0 : 0.f;
            float p1 = (kcol + 1 <= qrow0) ? __expf(s[nb][1] * 0.125f - m0) * iv0 : 0.f;
            float p2 = (kcol     <= qrow1) ? __expf(s[nb][2] * 0.125f - m1) * iv1 : 0.f;
            float p3 = (kcol + 1 <= qrow1) ? __expf(s[nb][3] * 0.125f - m1) * iv1 : 0.f;
            float2 w0; w0.x = p0; w0.y = p1;
            float2 w1; w1.x = p2; w1.y = p3;
            *(float2*)&sblk[(size_t)lr0 * T + kcol] = w0;
            *(float2*)&sblk[(size_t)lr1 * T + kcol] = w1;
            bf16 h0 = __float2bfloat16(p0), h1b = __float2bfloat16(p1);
            bf16 h2 = __float2bfloat16(p2), h3 = __float2bfloat16(p3);
            float l0f = p0 - __bfloat162float(h0), l1f = p1 - __bfloat162float(h1b);
            float l2f = p2 - __bfloat162float(h2), l3f = p3 - __bfloat162float(h3);
            int j = nb >> 1, hf = (nb & 1) * 2;
            bf162 t0; t0.x = h0; t0.y = h1b;
            bf162 t1; t1.x = h2; t1.y = h3;
            pa_h[j][hf]     = *(uint32_t*)&t0;
            pa_h[j][hf + 1] = *(uint32_t*)&t1;
            pa_l[j][hf]     = packbf(l0f, l1f);
            pa_l[j][hf + 1] = packbf(l2f, l3f);
        }

#pragma unroll
        for (int j = 0; j < 4; j++) {
            uint32_t vbh[4][4], vbl[4][4];
#pragma unroll
            for (int ns = 0; ns < 4; ns++) {
                uint32_t off = ((j * 16 + v_k) * FK + ns * 16 + v_n) * 2;
                LDSM4T(vbh[ns][0], vbh[ns][1], vbh[ns][2], vbh[ns][3], uVh + off);
                LDSM4T(vbl[ns][0], vbl[ns][1], vbl[ns][2], vbl[ns][3], uVl + off);
            }
#pragma unroll
            for (int nb = 0; nb < 8; nb++) {
                int n2 = nb >> 1, oo = (nb & 1) * 2;
                MMA16816(o[nb], pa_h[j], vbh[n2][oo], vbh[n2][oo + 1]);
                MMA16816(o[nb], pa_h[j], vbl[n2][oo], vbl[n2][oo + 1]);
                MMA16816(o[nb], pa_l[j], vbh[n2][oo], vbh[n2][oo + 1]);
            }
        }
        __syncthreads();
    }

    {
        int c0u = (qt + 1) * 128;
        int r = tid >> 1, hf = tid & 1;
        float4 z = make_float4(0.f, 0.f, 0.f, 0.f);
        for (int cc = c0u + hf * 4; cc < T; cc += 8)
            *(float4*)&sblk[(size_t)r * T + cc] = z;
    }

#pragma unroll
    for (int nb = 0; nb < 8; nb++) {
        int d = nb * 8 + (lane & 3) * 2;
        size_t i0 = ((size_t)(b * T + qrow0)) * D_MODEL + h * DH + d;
        size_t i1 = ((size_t)(b * T + qrow1)) * D_MODEL + h * DH + d;
        float y0 = o[nb][0], y1 = o[nb][1], y2 = o[nb][2], y3 = o[nb][3];
        bf16 h0 = __float2bfloat16(y0), h1b = __float2bfloat16(y1);
        bf16 h2 = __float2bfloat16(y2), h3 = __float2bfloat16(y3);
        bf162 hv0; hv0.x = h0; hv0.y = h1b;
        bf162 hv1; hv1.x = h2; hv1.y = h3;
        *(bf162*)&ohi[i0] = hv0;
        *(bf162*)&ohi[i1] = hv1;
        bf162 lv0, lv1;
        lv0.x = __float2bfloat16(y0 - __bfloat162float(h0));
        lv0.y = __float2bfloat16(y1 - __bfloat162float(h1b));
        lv1.x = __float2bfloat16(y2 - __bfloat162float(h2));
        lv1.y = __float2bfloat16(y3 - __bfloat162float(h3));
        *(bf162*)&olo[i0] = lv0;
        *(bf162*)&olo[i1] = lv1;
    }
}

// ---------------------------------------------------------------------------
extern "C" void kernel_launch(void* const* d_in, const int* in_sizes, int n_in,
                              void* d_out, int out_size) {
    (void)in_sizes; (void)n_in; (void)out_size;
    const float* x     = (const float*)d_in[0];
    const float* ln_g  = (const float*)d_in[1];
    const float* ln_b  = (const float*)d_in[2];
    const float* qkv_w = (const float*)d_in[3];
    const float* qkv_b = (const float*)d_in[4];
    const float* out_w = (const float*)d_in[5];
    const float* out_b = (const float*)d_in[6];

    float* xout = (float*)d_out;
    float* attn = xout + (size_t)BT * D_MODEL;

    static bf16 *p_hhi = nullptr, *p_hlo, *p_wqh, *p_wql, *p_woh, *p_wol;
    static bf16 *p_qh, *p_ql, *p_kh, *p_kl, *p_vh, *p_vl, *p_aoh, *p_aol;
    static float2* p_part;
    static float *p_m, *p_inv;
    if (!p_hhi) {
        cudaGetSymbolAddress((void**)&p_hhi, g_h_hi);
        cudaGetSymbolAddress((void**)&p_hlo, g_h_lo);
        cudaGetSymbolAddress((void**)&p_wqh, g_wq_hi);
        cudaGetSymbolAddress((void**)&p_wql, g_wq_lo);
        cudaGetSymbolAddress((void**)&p_woh, g_wo_hi);
        cudaGetSymbolAddress((void**)&p_wol, g_wo_lo);
        cudaGetSymbolAddress((void**)&p_qh, g_q_hi);
        cudaGetSymbolAddress((void**)&p_ql, g_q_lo);
        cudaGetSymbolAddress((void**)&p_kh, g_k_hi);
        cudaGetSymbolAddress((void**)&p_kl, g_k_lo);
        cudaGetSymbolAddress((void**)&p_vh, g_v_hi);
        cudaGetSymbolAddress((void**)&p_vl, g_v_lo);
        cudaGetSymbolAddress((void**)&p_aoh, g_ao_hi);
        cudaGetSymbolAddress((void**)&p_aol, g_ao_lo);
        cudaGetSymbolAddress((void**)&p_part, g_part);
        cudaGetSymbolAddress((void**)&p_m, g_m);
        cudaGetSymbolAddress((void**)&p_inv, g_inv);
        cudaFuncSetAttribute(gemm_mma_qkv, cudaFuncAttributeMaxDynamicSharedMemorySize, G_SMEM);
        cudaFuncSetAttribute(gemm_mma_out, cudaFuncAttributeMaxDynamicSharedMemorySize, G_SMEM);
        cudaFuncSetAttribute(scores_stats, cudaFuncAttributeMaxDynamicSharedMemorySize, SCORES_SMEM);
        cudaFuncSetAttribute(av_fused, cudaFuncAttributeMaxDynamicSharedMemorySize, FA_SMEM);
    }

    ln_kernel<<<BT, 256>>>(x, ln_g, ln_b, p_hhi, p_hlo);
    tsplit_kernel<<<dim3(QKV_N / 32, D_MODEL / 32), dim3(32, 8)>>>(qkv_w, p_wqh, p_wql, D_MODEL, QKV_N);
    tsplit_kernel<<<dim3(D_MODEL / 32, D_MODEL / 32), dim3(32, 8)>>>(out_w, p_woh, p_wol, D_MODEL, D_MODEL);

    gemm_mma_qkv<<<dim3(QKV_N / 128, BT / 256), 512, G_SMEM>>>(
        p_hhi, p_hlo, p_wqh, p_wql, qkv_b, p_qh, p_ql, p_kh, p_kl, p_vh, p_vl);

    scores_stats<<<dim3(16, 16, 32), 256, SCORES_SMEM>>>(p_qh, p_ql, p_kh, p_kl, p_part);
    reduce_stats<<<(32 * T) / 256, 256>>>(p_part, p_m, p_inv);
    av_fused<<<dim3(16, 32), 256, FA_SMEM>>>(p_qh, p_ql, p_kh, p_kl, p_vh, p_vl,
                                             p_m, p_inv, attn, p_aoh, p_aol);

    gemm_mma_out<<<dim3(D_MODEL / 128, BT / 256), 512, G_SMEM>>>(
        p_aoh, p_aol, p_woh, p_wol, out_b, x, xout);
}

// round 17
// speedup vs baseline: 1.6425x; 1.0251x over previous
#include <cuda_runtime.h>
#include <cuda_bf16.h>
#include <cstdint>
#include <math.h>

#define D_MODEL 1024
#define NH      16
#define DH      64
#define BATCH   2
#define T       2048
#define BT      4096
#define QKV_N   3072

typedef __nv_bfloat16 bf16;
typedef __nv_bfloat162 bf162;

// ---------------------------------------------------------------------------
// Scratch
// ---------------------------------------------------------------------------
__device__ bf16 g_h_hi[(size_t)BT * D_MODEL];
__device__ bf16 g_h_lo[(size_t)BT * D_MODEL];
__device__ bf16 g_wq_hi[(size_t)QKV_N * D_MODEL];
__device__ bf16 g_wq_lo[(size_t)QKV_N * D_MODEL];
__device__ bf16 g_wo_hi[(size_t)D_MODEL * D_MODEL];
__device__ bf16 g_wo_lo[(size_t)D_MODEL * D_MODEL];
__device__ bf16 g_q_hi[(size_t)32 * T * DH];
__device__ bf16 g_q_lo[(size_t)32 * T * DH];
__device__ bf16 g_k_hi[(size_t)32 * T * DH];
__device__ bf16 g_k_lo[(size_t)32 * T * DH];
__device__ bf16 g_v_hi[(size_t)32 * T * DH];
__device__ bf16 g_v_lo[(size_t)32 * T * DH];
__device__ bf16 g_ao_hi[(size_t)BT * D_MODEL];
__device__ bf16 g_ao_lo[(size_t)BT * D_MODEL];
__device__ float  g_m[(size_t)32 * T];
__device__ float  g_inv[(size_t)32 * T];

// ---------------------------------------------------------------------------
// Helpers
// ---------------------------------------------------------------------------
__device__ __forceinline__ uint32_t smem_u32(const void* p) {
    uint32_t a;
    asm("{ .reg .u64 t; cvta.to.shared.u64 t, %1; cvt.u32.u64 %0, t; }" : "=r"(a) : "l"(p));
    return a;
}
__device__ __forceinline__ void cp16(uint32_t dst, const void* src) {
    asm volatile("cp.async.cg.shared.global [%0], [%1], 16;" :: "r"(dst), "l"(src));
}
#define CP_COMMIT() asm volatile("cp.async.commit_group;" ::: "memory")
#define CP_WAIT0()  asm volatile("cp.async.wait_group 0;" ::: "memory")
#define CP_WAIT1()  asm volatile("cp.async.wait_group 1;" ::: "memory")
#define LDSM4(r0, r1, r2, r3, addr)                                              \
    asm volatile("ldmatrix.sync.aligned.m8n8.x4.shared.b16 {%0,%1,%2,%3}, [%4];" \
                 : "=r"(r0), "=r"(r1), "=r"(r2), "=r"(r3) : "r"(addr))
#define LDSM4T(r0, r1, r2, r3, addr)                                                   \
    asm volatile("ldmatrix.sync.aligned.m8n8.x4.trans.shared.b16 {%0,%1,%2,%3}, [%4];" \
                 : "=r"(r0), "=r"(r1), "=r"(r2), "=r"(r3) : "r"(addr))
#define MMA16816(c, a, b0, b1)                                                   \
    asm volatile("mma.sync.aligned.m16n8k16.row.col.f32.bf16.bf16.f32 "          \
                 "{%0,%1,%2,%3}, {%4,%5,%6,%7}, {%8,%9}, {%0,%1,%2,%3};"         \
                 : "+f"((c)[0]), "+f"((c)[1]), "+f"((c)[2]), "+f"((c)[3])        \
                 : "r"((a)[0]), "r"((a)[1]), "r"((a)[2]), "r"((a)[3]),           \
                   "r"(b0), "r"(b1))

__device__ __forceinline__ void ms_merge(float& m, float& s, float om, float os) {
    float M = fmaxf(m, om);
    s = s * __expf(m - M) + os * __expf(om - M);
    m = M;
}
__device__ __forceinline__ uint32_t packbf(float a, float b) {
    bf162 v; v.x = __float2bfloat16(a); v.y = __float2bfloat16(b);
    return *(uint32_t*)&v;
}

// ---------------------------------------------------------------------------
// LayerNorm -> bf16 hi/lo split
// ---------------------------------------------------------------------------
__global__ void ln_kernel(const float* __restrict__ x, const float* __restrict__ gam,
                          const float* __restrict__ bet,
                          bf16* __restrict__ ohi, bf16* __restrict__ olo) {
    int row = blockIdx.x;
    const float* xr = x + (size_t)row * D_MODEL;
    float v[4];
    float s = 0.f, s2 = 0.f;
#pragma unroll
    for (int i = 0; i < 4; i++) {
        v[i] = xr[threadIdx.x + i * 256];
        s += v[i]; s2 += v[i] * v[i];
    }
#pragma unroll
    for (int o = 16; o > 0; o >>= 1) {
        s  += __shfl_xor_sync(~0u, s, o);
        s2 += __shfl_xor_sync(~0u, s2, o);
    }
    __shared__ float rs[8], rs2[8];
    int wid = threadIdx.x >> 5, lid = threadIdx.x & 31;
    if (lid == 0) { rs[wid] = s; rs2[wid] = s2; }
    __syncthreads();
    s = 0.f; s2 = 0.f;
#pragma unroll
    for (int i = 0; i < 8; i++) { s += rs[i]; s2 += rs2[i]; }
    float mu  = s * (1.f / D_MODEL);
    float var = s2 * (1.f / D_MODEL) - mu * mu;
    float inv = rsqrtf(var + 1e-5f);
#pragma unroll
    for (int i = 0; i < 4; i++) {
        int c = threadIdx.x + i * 256;
        float y = (v[i] - mu) * inv * gam[c] + bet[c];
        bf16 h = __float2bfloat16(y);
        ohi[(size_t)row * D_MODEL + c] = h;
        olo[(size_t)row * D_MODEL + c] = __float2bfloat16(y - __bfloat162float(h));
    }
}

// ---------------------------------------------------------------------------
// Transpose + bf16 split: W[K][N] -> out[N][K]
// ---------------------------------------------------------------------------
__global__ void tsplit_kernel(const float* __restrict__ W,
                              bf16* __restrict__ hi, bf16* __restrict__ lo,
                              int K, int N) {
    __shared__ float t[32][33];
    int n0 = blockIdx.x * 32, k0 = blockIdx.y * 32;
    int tx = threadIdx.x, ty = threadIdx.y;
#pragma unroll
    for (int j = 0; j < 4; j++)
        t[ty + j * 8][tx] = W[(size_t)(k0 + ty + j * 8) * N + n0 + tx];
    __syncthreads();
#pragma unroll
    for (int j = 0; j < 4; j++) {
        float v = t[tx][ty + j * 8];
        size_t o = (size_t)(n0 + ty + j * 8) * K + k0 + tx;
        bf16 h = __float2bfloat16(v);
        hi[o] = h;
        lo[o] = __float2bfloat16(v - __bfloat162float(h));
    }
}

// ---------------------------------------------------------------------------
// Dense GEMMs (unchanged from R16): 512 thr, 256x128x64, warp tile 64x32.
// ---------------------------------------------------------------------------
#define SA 72
#define GA_T   (256 * SA * 2)
#define GB_T   (128 * SA * 2)
#define G_STG  (2 * GA_T + 2 * GB_T)
#define G_SMEM (2 * G_STG)

__device__ __forceinline__ void g2_issue(
    uint32_t sb, int st, int kc, int bm, int bn, int tid, int K,
    const bf16* __restrict__ Ah, const bf16* __restrict__ Al,
    const bf16* __restrict__ Bh, const bf16* __restrict__ Bl) {
    int c0 = kc * 64;
    uint32_t base = sb + (uint32_t)st * G_STG;
#pragma unroll
    for (int it = 0; it < 4; it++) {
        int idx = tid + it * 512;
        int r = idx >> 3, cc = (idx & 7) * 8;
        size_t ga = (size_t)(bm * 256 + r) * K + c0 + cc;
        uint32_t so = (uint32_t)(r * SA + cc) * 2;
        cp16(base + so, Ah + ga);
        cp16(base + GA_T + so, Al + ga);
    }
#pragma unroll
    for (int it = 0; it < 2; it++) {
        int idx = tid + it * 512;
        int r = idx >> 3, cc = (idx & 7) * 8;
        size_t gb = (size_t)(bn * 128 + r) * K + c0 + cc;
        uint32_t so = (uint32_t)(r * SA + cc) * 2;
        cp16(base + 2 * GA_T + so, Bh + gb);
        cp16(base + 2 * GA_T + GB_T + so, Bl + gb);
    }
    CP_COMMIT();
}

#define G2_MAINLOOP(K_)                                                          \
    int a_row = wm * 64 + ((lane >> 3) & 1) * 8 + (lane & 7);                    \
    int a_kc  = (lane >> 4) * 8;                                                 \
    int b_row = wn * 32 + (lane >> 4) * 8 + (lane & 7);                          \
    int b_kc  = ((lane >> 3) & 1) * 8;                                           \
    float c[4][4][4];                                                            \
    _Pragma("unroll") for (int i = 0; i < 4; i++)                                \
    _Pragma("unroll") for (int j = 0; j < 4; j++)                                \
    _Pragma("unroll") for (int q = 0; q < 4; q++) c[i][j][q] = 0.f;              \
    const int NK = (K_) / 64;                                                    \
    g2_issue(sb, 0, 0, bm, bn, tid, (K_), Ah, Al, Bh, Bl);                       \
    for (int kc = 0; kc < NK; kc++) {                                            \
        if (kc + 1 < NK) { g2_issue(sb, (kc + 1) & 1, kc + 1, bm, bn, tid,       \
                                    (K_), Ah, Al, Bh, Bl); CP_WAIT1(); }         \
        else CP_WAIT0();                                                         \
        __syncthreads();                                                         \
        uint32_t uAh = sb + (uint32_t)(kc & 1) * G_STG;                          \
        uint32_t uAl = uAh + GA_T;                                               \
        uint32_t uBh = uAh + 2 * GA_T;                                           \
        uint32_t uBl = uBh + GB_T;                                               \
        _Pragma("unroll")                                                        \
        for (int ks = 0; ks < 4; ks++) {                                         \
            uint32_t bh[2][4], bl[2][4];                                         \
            _Pragma("unroll")                                                    \
            for (int nb2 = 0; nb2 < 2; nb2++) {                                  \
                uint32_t off = ((b_row + nb2 * 16) * SA + b_kc + ks * 16) * 2;   \
                LDSM4(bh[nb2][0], bh[nb2][1], bh[nb2][2], bh[nb2][3], uBh + off);\
                LDSM4(bl[nb2][0], bl[nb2][1], bl[nb2][2], bl[nb2][3], uBl + off);\
            }                                                                    \
            _Pragma("unroll")                                                    \
            for (int ma = 0; ma < 4; ma++) {                                     \
                uint32_t ah[4], al[4];                                           \
                uint32_t off = ((a_row + ma * 16) * SA + a_kc + ks * 16) * 2;    \
                LDSM4(ah[0], ah[1], ah[2], ah[3], uAh + off);                    \
                LDSM4(al[0], al[1], al[2], al[3], uAl + off);                    \
                _Pragma("unroll")                                                \
                for (int nb = 0; nb < 4; nb++) {                                 \
                    int n2 = nb >> 1, o = (nb & 1) * 2;                          \
                    MMA16816(c[ma][nb], ah, bh[n2][o], bh[n2][o + 1]);           \
                    MMA16816(c[ma][nb], ah, bl[n2][o], bl[n2][o + 1]);           \
                    MMA16816(c[ma][nb], al, bh[n2][o], bh[n2][o + 1]);           \
                }                                                                \
            }                                                                    \
        }                                                                        \
        __syncthreads();                                                         \
    }

__global__ void __launch_bounds__(512) gemm_mma_qkv(
    const bf16* __restrict__ Ah, const bf16* __restrict__ Al,
    const bf16* __restrict__ Bh, const bf16* __restrict__ Bl,
    const float* __restrict__ bias,
    bf16* __restrict__ qhi, bf16* __restrict__ qlo,
    bf16* __restrict__ khi, bf16* __restrict__ klo,
    bf16* __restrict__ vhi, bf16* __restrict__ vlo) {
    extern __shared__ char dyn[];
    uint32_t sb = smem_u32(dyn);
    int tid = threadIdx.x;
    int wid = tid >> 5, lane = tid & 31;
    int wm = wid & 3, wn = wid >> 2;
    int bm = blockIdx.y, bn = blockIdx.x;

    G2_MAINLOOP(D_MODEL)

    int r0 = bm * 256 + wm * 64 + (lane >> 2);
#pragma unroll
    for (int ma = 0; ma < 4; ma++) {
#pragma unroll
        for (int nb = 0; nb < 4; nb++) {
            int col = bn * 128 + wn * 32 + nb * 8 + (lane & 3) * 2;
            int hg = col >> 6;
            int sec = hg >> 4;
            int h = hg & 15;
            int c64 = col & 63;
            bf16* dh = (sec == 0) ? qhi : (sec == 1) ? khi : vhi;
            bf16* dl = (sec == 0) ? qlo : (sec == 1) ? klo : vlo;
            float bx = bias[col], by = bias[col + 1];
#pragma unroll
            for (int half = 0; half < 2; half++) {
                int row = r0 + ma * 16 + half * 8;
                int t = row & (T - 1), b = row >> 11;
                size_t idx = (((size_t)(b * NH + h)) * T + t) * DH + c64;
                float y0 = c[ma][nb][half * 2 + 0] + bx;
                float y1 = c[ma][nb][half * 2 + 1] + by;
                bf16 h0 = __float2bfloat16(y0);
                bf16 h1 = __float2bfloat16(y1);
                bf162 hv; hv.x = h0; hv.y = h1;
                bf162 lv;
                lv.x = __float2bfloat16(y0 - __bfloat162float(h0));
                lv.y = __float2bfloat16(y1 - __bfloat162float(h1));
                *(bf162*)&dh[idx] = hv;
                *(bf162*)&dl[idx] = lv;
            }
        }
    }
}

__global__ void __launch_bounds__(512) gemm_mma_out(
    const bf16* __restrict__ Ah, const bf16* __restrict__ Al,
    const bf16* __restrict__ Bh, const bf16* __restrict__ Bl,
    const float* __restrict__ bias, const float* __restrict__ res,
    float* __restrict__ C) {
    const int N = D_MODEL;
    extern __shared__ char dyn[];
    uint32_t sb = smem_u32(dyn);
    int tid = threadIdx.x;
    int wid = tid >> 5, lane = tid & 31;
    int wm = wid & 3, wn = wid >> 2;
    int bm = blockIdx.y, bn = blockIdx.x;

    G2_MAINLOOP(D_MODEL)

    int r0 = bm * 256 + wm * 64 + (lane >> 2);
#pragma unroll
    for (int ma = 0; ma < 4; ma++) {
#pragma unroll
        for (int nb = 0; nb < 4; nb++) {
            int col = bn * 128 + wn * 32 + nb * 8 + (lane & 3) * 2;
            int ra = r0 + ma * 16, rb = ra + 8;
            float2 o0, o1;
            o0.x = c[ma][nb][0] + bias[col];
            o0.y = c[ma][nb][1] + bias[col + 1];
            o1.x = c[ma][nb][2] + bias[col];
            o1.y = c[ma][nb][3] + bias[col + 1];
            float2 r2a = *(const float2*)&res[(size_t)ra * N + col];
            float2 r2b = *(const float2*)&res[(size_t)rb * N + col];
            o0.x += r2a.x; o0.y += r2a.y;
            o1.x += r2b.x; o1.y += r2b.y;
            *(float2*)&C[(size_t)ra * N + col] = o0;
            *(float2*)&C[(size_t)rb * N + col] = o1;
        }
    }
}

// ---------------------------------------------------------------------------
// Persistent stats pass: one block per (qt, bh), K streamed in 64-chunks.
// Q frags in regs; running (m, sum) per thread-row; writes g_m/g_inv directly.
// ---------------------------------------------------------------------------
#define FK 72
#define FA_QT2  (128 * FK * 2)            // 18432
#define FA_KT2  (64 * FK * 2)             // 9216
#define ST_STG  (2 * FA_KT2)              // 18432 (Kh,Kl)
#define FA_KV   (2 * FA_QT2)              // 36864
#define ST_SMEM (FA_KV + 2 * ST_STG)      // 73728

__device__ __forceinline__ void st_issue_k(
    uint32_t sb, int st, int kt, int tid,
    const bf16* __restrict__ kh, const bf16* __restrict__ kl) {
    uint32_t base = sb + FA_KV + (uint32_t)st * ST_STG;
#pragma unroll
    for (int p = 0; p < 2; p++) {
        int idx = tid + p * 256;
        int r = idx >> 3, cc = (idx & 7) * 8;
        size_t g = (size_t)(kt * 64 + r) * DH + cc;
        uint32_t so = (uint32_t)(r * FK + cc) * 2;
        cp16(base + so, kh + g);
        cp16(base + FA_KT2 + so, kl + g);
    }
    CP_COMMIT();
}

__global__ void __launch_bounds__(256) scores_stats(
    const bf16* __restrict__ qhA, const bf16* __restrict__ qlA,
    const bf16* __restrict__ khA, const bf16* __restrict__ klA,
    float* __restrict__ mA, float* __restrict__ invA) {
    int qt = 15 - blockIdx.x;            // descending: heavy CTAs first
    int bh = blockIdx.y;
    int tid = threadIdx.x;
    int wid = tid >> 5, lane = tid & 31;

    extern __shared__ char dyn[];
    uint32_t sb = smem_u32(dyn);

    const bf16* qh = qhA + ((size_t)bh * T + qt * 128) * DH;
    const bf16* ql = qlA + ((size_t)bh * T + qt * 128) * DH;
    const bf16* kh = khA + (size_t)bh * T * DH;
    const bf16* kl = klA + (size_t)bh * T * DH;

    int lr0 = wid * 16 + (lane >> 2);
    int lr1 = lr0 + 8;
    int qrow0 = qt * 128 + lr0, qrow1 = qt * 128 + lr1;

    {
#pragma unroll
        for (int p = 0; p < 4; p++) {
            int idx = tid + p * 256;
            int r = idx >> 3, cc = (idx & 7) * 8;
            size_t g = (size_t)r * DH + cc;
            uint32_t so = (uint32_t)(r * FK + cc) * 2;
            cp16(sb + so, qh + g);
            cp16(sb + FA_QT2 + so, ql + g);
        }
        CP_COMMIT();
    }
    st_issue_k(sb, 0, 0, tid, kh, kl);

    int a_row = wid * 16 + ((lane >> 3) & 1) * 8 + (lane & 7);
    int a_kc  = (lane >> 4) * 8;
    int b_row8 = (lane >> 4) * 8 + (lane & 7);
    int b_kc  = ((lane >> 3) & 1) * 8;

    uint32_t qa_h[4][4], qa_l[4][4];
    float m0r = -1e30f, s0r = 0.f, m1r = -1e30f, s1r = 0.f;

    int nk = 2 * qt + 2;
    for (int kt = 0; kt < nk; kt++) {
        if (kt + 1 < nk) { st_issue_k(sb, (kt + 1) & 1, kt + 1, tid, kh, kl); CP_WAIT1(); }
        else CP_WAIT0();
        __syncthreads();

        if (kt == 0) {
#pragma unroll
            for (int ks = 0; ks < 4; ks++) {
                uint32_t off = (a_row * FK + a_kc + ks * 16) * 2;
                LDSM4(qa_h[ks][0], qa_h[ks][1], qa_h[ks][2], qa_h[ks][3], sb + off);
                LDSM4(qa_l[ks][0], qa_l[ks][1], qa_l[ks][2], qa_l[ks][3], sb + FA_QT2 + off);
            }
        }

        uint32_t uKh = sb + FA_KV + (uint32_t)(kt & 1) * ST_STG;
        uint32_t uKl = uKh + FA_KT2;

        float s[8][4];
#pragma unroll
        for (int i = 0; i < 8; i++)
#pragma unroll
            for (int q = 0; q < 4; q++) s[i][q] = 0.f;

#pragma unroll
        for (int ks = 0; ks < 4; ks++) {
            uint32_t kbh[4][4], kbl[4][4];
#pragma unroll
            for (int nb2 = 0; nb2 < 4; nb2++) {
                uint32_t off = ((nb2 * 16 + b_row8) * FK + b_kc + ks * 16) * 2;
                LDSM4(kbh[nb2][0], kbh[nb2][1], kbh[nb2][2], kbh[nb2][3], uKh + off);
                LDSM4(kbl[nb2][0], kbl[nb2][1], kbl[nb2][2], kbl[nb2][3], uKl + off);
            }
#pragma unroll
            for (int nb = 0; nb < 8; nb++) {
                int n2 = nb >> 1, oo = (nb & 1) * 2;
                MMA16816(s[nb], qa_h[ks], kbh[n2][oo], kbh[n2][oo + 1]);
                MMA16816(s[nb], qa_h[ks], kbl[n2][oo], kbl[n2][oo + 1]);
                MMA16816(s[nb], qa_l[ks], kbh[n2][oo], kbh[n2][oo + 1]);
            }
        }

        // chunk-local stats per thread-row, merged into running
        float v0[8][2], v1[8][2];
#pragma unroll
        for (int nb = 0; nb < 8; nb++) {
            int kcol = kt * 64 + nb * 8 + (lane & 3) * 2;
            v0[nb][0] = (kcol     <= qrow0) ? s[nb][0] * 0.125f : -1e30f;
            v0[nb][1] = (kcol + 1 <= qrow0) ? s[nb][1] * 0.125f : -1e30f;
            v1[nb][0] = (kcol     <= qrow1) ? s[nb][2] * 0.125f : -1e30f;
            v1[nb][1] = (kcol + 1 <= qrow1) ? s[nb][3] * 0.125f : -1e30f;
        }
        float mt0 = -1e30f, mt1 = -1e30f;
#pragma unroll
        for (int nb = 0; nb < 8; nb++) {
            mt0 = fmaxf(mt0, fmaxf(v0[nb][0], v0[nb][1]));
            mt1 = fmaxf(mt1, fmaxf(v1[nb][0], v1[nb][1]));
        }
        float st0 = 0.f, st1 = 0.f;
#pragma unroll
        for (int nb = 0; nb < 8; nb++) {
            st0 += __expf(v0[nb][0] - mt0) + __expf(v0[nb][1] - mt0);
            st1 += __expf(v1[nb][0] - mt1) + __expf(v1[nb][1] - mt1);
        }
        ms_merge(m0r, s0r, mt0, st0);
        ms_merge(m1r, s1r, mt1, st1);
        __syncthreads();
    }

    // merge across the 4 lanes sharing each row
#pragma unroll
    for (int o = 1; o < 4; o <<= 1) {
        float om0 = __shfl_xor_sync(~0u, m0r, o);
        float os0 = __shfl_xor_sync(~0u, s0r, o);
        ms_merge(m0r, s0r, om0, os0);
        float om1 = __shfl_xor_sync(~0u, m1r, o);
        float os1 = __shfl_xor_sync(~0u, s1r, o);
        ms_merge(m1r, s1r, om1, os1);
    }
    if ((lane & 3) == 0) {
        mA[bh * T + qrow0] = m0r;
        invA[bh * T + qrow0] = 1.f / s0r;
        mA[bh * T + qrow1] = m1r;
        invA[bh * T + qrow1] = 1.f / s1r;
    }
}

// ---------------------------------------------------------------------------
// Fused av (R16 proven; qt descending)
// ---------------------------------------------------------------------------
#define FA_STG  (4 * FA_KT2)
#define FA_SMEM (FA_KV + 2 * FA_STG)

__device__ __forceinline__ void fa_issue_kv(
    uint32_t sb, int st, int kt, int tid,
    const bf16* __restrict__ kh, const bf16* __restrict__ kl,
    const bf16* __restrict__ vh, const bf16* __restrict__ vl) {
    uint32_t base = sb + FA_KV + (uint32_t)st * FA_STG;
#pragma unroll
    for (int p = 0; p < 2; p++) {
        int idx = tid + p * 256;
        int r = idx >> 3, cc = (idx & 7) * 8;
        size_t g = (size_t)(kt * 64 + r) * DH + cc;
        uint32_t so = (uint32_t)(r * FK + cc) * 2;
        cp16(base + so, kh + g);
        cp16(base + FA_KT2 + so, kl + g);
        cp16(base + 2 * FA_KT2 + so, vh + g);
        cp16(base + 3 * FA_KT2 + so, vl + g);
    }
    CP_COMMIT();
}

__global__ void __launch_bounds__(256) av_fused(
    const bf16* __restrict__ qhA, const bf16* __restrict__ qlA,
    const bf16* __restrict__ khA, const bf16* __restrict__ klA,
    const bf16* __restrict__ vhA, const bf16* __restrict__ vlA,
    const float* __restrict__ mA, const float* __restrict__ invA,
    float* __restrict__ attn,
    bf16* __restrict__ ohi, bf16* __restrict__ olo) {
    int qt = 15 - blockIdx.x;            // descending: heavy CTAs first
    int bh = blockIdx.y;
    int b = bh >> 4, h = bh & 15;
    int tid = threadIdx.x;
    int wid = tid >> 5, lane = tid & 31;

    extern __shared__ char dyn[];
    uint32_t sb = smem_u32(dyn);

    const bf16* qh = qhA + ((size_t)bh * T + qt * 128) * DH;
    const bf16* ql = qlA + ((size_t)bh * T + qt * 128) * DH;
    const bf16* kh = khA + (size_t)bh * T * DH;
    const bf16* kl = klA + (size_t)bh * T * DH;
    const bf16* vh = vhA + (size_t)bh * T * DH;
    const bf16* vl = vlA + (size_t)bh * T * DH;
    float* sblk = attn + ((size_t)bh * T + qt * 128) * T;

    int lr0 = wid * 16 + (lane >> 2);
    int lr1 = lr0 + 8;
    int qrow0 = qt * 128 + lr0, qrow1 = qt * 128 + lr1;
    float m0 = mA[bh * T + qrow0], iv0 = invA[bh * T + qrow0];
    float m1 = mA[bh * T + qrow1], iv1 = invA[bh * T + qrow1];

    {
#pragma unroll
        for (int p = 0; p < 4; p++) {
            int idx = tid + p * 256;
            int r = idx >> 3, cc = (idx & 7) * 8;
            size_t g = (size_t)r * DH + cc;
            uint32_t so = (uint32_t)(r * FK + cc) * 2;
            cp16(sb + so, qh + g);
            cp16(sb + FA_QT2 + so, ql + g);
        }
        CP_COMMIT();
    }
    fa_issue_kv(sb, 0, 0, tid, kh, kl, vh, vl);

    int a_row = wid * 16 + ((lane >> 3) & 1) * 8 + (lane & 7);
    int a_kc  = (lane >> 4) * 8;
    int b_row8 = (lane >> 4) * 8 + (lane & 7);
    int b_kc  = ((lane >> 3) & 1) * 8;
    int v_k   = lane & 15;
    int v_n   = (lane >> 4) * 8;

    uint32_t qa_h[4][4], qa_l[4][4];
    float o[8][4];
#pragma unroll
    for (int i = 0; i < 8; i++)
#pragma unroll
        for (int q = 0; q < 4; q++) o[i][q] = 0.f;

    int nk = 2 * qt + 2;
    for (int kt = 0; kt < nk; kt++) {
        if (kt + 1 < nk) { fa_issue_kv(sb, (kt + 1) & 1, kt + 1, tid, kh, kl, vh, vl); CP_WAIT1(); }
        else CP_WAIT0();
        __syncthreads();

        if (kt == 0) {
#pragma unroll
            for (int ks = 0; ks < 4; ks++) {
                uint32_t off = (a_row * FK + a_kc + ks * 16) * 2;
                LDSM4(qa_h[ks][0], qa_h[ks][1], qa_h[ks][2], qa_h[ks][3], sb + off);
                LDSM4(qa_l[ks][0], qa_l[ks][1], qa_l[ks][2], qa_l[ks][3], sb + FA_QT2 + off);
            }
        }

        uint32_t uKh = sb + FA_KV + (uint32_t)(kt & 1) * FA_STG;
        uint32_t uKl = uKh + FA_KT2;
        uint32_t uVh = uKh + 2 * FA_KT2;
        uint32_t uVl = uKh + 3 * FA_KT2;

        float s[8][4];
#pragma unroll
        for (int i = 0; i < 8; i++)
#pragma unroll
            for (int q = 0; q < 4; q++) s[i][q] = 0.f;

#pragma unroll
        for (int ks = 0; ks < 4; ks++) {
            uint32_t kbh[4][4], kbl[4][4];
#pragma unroll
            for (int nb2 = 0; nb2 < 4; nb2++) {
                uint32_t off = ((nb2 * 16 + b_row8) * FK + b_kc + ks * 16) * 2;
                LDSM4(kbh[nb2][0], kbh[nb2][1], kbh[nb2][2], kbh[nb2][3], uKh + off);
                LDSM4(kbl[nb2][0], kbl[nb2][1], kbl[nb2][2], kbl[nb2][3], uKl + off);
            }
#pragma unroll
            for (int nb = 0; nb < 8; nb++) {
                int n2 = nb >> 1, oo = (nb & 1) * 2;
                MMA16816(s[nb], qa_h[ks], kbh[n2][oo], kbh[n2][oo + 1]);
                MMA16816(s[nb], qa_h[ks], kbl[n2][oo], kbl[n2][oo + 1]);
                MMA16816(s[nb], qa_l[ks], kbh[n2][oo], kbh[n2][oo + 1]);
            }
        }

        uint32_t pa_h[4][4], pa_l[4][4];
#pragma unroll
        for (int nb = 0; nb < 8; nb++) {
            int kcol = kt * 64 + nb * 8 + (lane & 3) * 2;
            float p0 = (kcol     <= qrow0) ? __expf(s[nb][0] * 0.125f - m0) * iv0 : 0.f;
            float p1 = (kcol + 1 <= qrow0) ? __expf(s[nb][1] * 0.125f - m0) * iv0 : 0.f;
            float p2 = (kcol     <= qrow1) ? __expf(s[nb][2] * 0.125f - m1) * iv1 : 0.f;
            float p3 = (kcol + 1 <= qrow1) ? __expf(s[nb][3] * 0.125f - m1) * iv1 : 0.f;
            float2 w0; w0.x = p0; w0.y = p1;
            float2 w1; w1.x = p2; w1.y = p3;
            *(float2*)&sblk[(size_t)lr0 * T + kcol] = w0;
            *(float2*)&sblk[(size_t)lr1 * T + kcol] = w1;
            bf16 h0 = __float2bfloat16(p0), h1b = __float2bfloat16(p1);
            bf16 h2 = __float2bfloat16(p2), h3 = __float2bfloat16(p3);
            float l0f = p0 - __bfloat162float(h0), l1f = p1 - __bfloat162float(h1b);
            float l2f = p2 - __bfloat162float(h2), l3f = p3 - __bfloat162float(h3);
            int j = nb >> 1, hf = (nb & 1) * 2;
            bf162 t0; t0.x = h0; t0.y = h1b;
            bf162 t1; t1.x = h2; t1.y = h3;
            pa_h[j][hf]     = *(uint32_t*)&t0;
            pa_h[j][hf + 1] = *(uint32_t*)&t1;
            pa_l[j][hf]     = packbf(l0f, l1f);
            pa_l[j][hf + 1] = packbf(l2f, l3f);
        }

#pragma unroll
        for (int j = 0; j < 4; j++) {
            uint32_t vbh[4][4], vbl[4][4];
#pragma unroll
            for (int ns = 0; ns < 4; ns++) {
                uint32_t off = ((j * 16 + v_k) * FK + ns * 16 + v_n) * 2;
                LDSM4T(vbh[ns][0], vbh[ns][1], vbh[ns][2], vbh[ns][3], uVh + off);
                LDSM4T(vbl[ns][0], vbl[ns][1], vbl[ns][2], vbl[ns][3], uVl + off);
            }
#pragma unroll
            for (int nb = 0; nb < 8; nb++) {
                int n2 = nb >> 1, oo = (nb & 1) * 2;
                MMA16816(o[nb], pa_h[j], vbh[n2][oo], vbh[n2][oo + 1]);
                MMA16816(o[nb], pa_h[j], vbl[n2][oo], vbl[n2][oo + 1]);
                MMA16816(o[nb], pa_l[j], vbh[n2][oo], vbh[n2][oo + 1]);
            }
        }
        __syncthreads();
    }

    {
        int c0u = (qt + 1) * 128;
        int r = tid >> 1, hf = tid & 1;
        float4 z = make_float4(0.f, 0.f, 0.f, 0.f);
        for (int cc = c0u + hf * 4; cc < T; cc += 8)
            *(float4*)&sblk[(size_t)r * T + cc] = z;
    }

#pragma unroll
    for (int nb = 0; nb < 8; nb++) {
        int d = nb * 8 + (lane & 3) * 2;
        size_t i0 = ((size_t)(b * T + qrow0)) * D_MODEL + h * DH + d;
        size_t i1 = ((size_t)(b * T + qrow1)) * D_MODEL + h * DH + d;
        float y0 = o[nb][0], y1 = o[nb][1], y2 = o[nb][2], y3 = o[nb][3];
        bf16 h0 = __float2bfloat16(y0), h1b = __float2bfloat16(y1);
        bf16 h2 = __float2bfloat16(y2), h3 = __float2bfloat16(y3);
        bf162 hv0; hv0.x = h0; hv0.y = h1b;
        bf162 hv1; hv1.x = h2; hv1.y = h3;
        *(bf162*)&ohi[i0] = hv0;
        *(bf162*)&ohi[i1] = hv1;
        bf162 lv0, lv1;
        lv0.x = __float2bfloat16(y0 - __bfloat162float(h0));
        lv0.y = __float2bfloat16(y1 - __bfloat162float(h1b));
        lv1.x = __float2bfloat16(y2 - __bfloat162float(h2));
        lv1.y = __float2bfloat16(y3 - __bfloat162float(h3));
        *(bf162*)&olo[i0] = lv0;
        *(bf162*)&olo[i1] = lv1;
    }
}

// ---------------------------------------------------------------------------
extern "C" void kernel_launch(void* const* d_in, const int* in_sizes, int n_in,
                              void* d_out, int out_size) {
    (void)in_sizes; (void)n_in; (void)out_size;
    const float* x     = (const float*)d_in[0];
    const float* ln_g  = (const float*)d_in[1];
    const float* ln_b  = (const float*)d_in[2];
    const float* qkv_w = (const float*)d_in[3];
    const float* qkv_b = (const float*)d_in[4];
    const float* out_w = (const float*)d_in[5];
    const float* out_b = (const float*)d_in[6];

    float* xout = (float*)d_out;
    float* attn = xout + (size_t)BT * D_MODEL;

    static bf16 *p_hhi = nullptr, *p_hlo, *p_wqh, *p_wql, *p_woh, *p_wol;
    static bf16 *p_qh, *p_ql, *p_kh, *p_kl, *p_vh, *p_vl, *p_aoh, *p_aol;
    static float *p_m, *p_inv;
    if (!p_hhi) {
        cudaGetSymbolAddress((void**)&p_hhi, g_h_hi);
        cudaGetSymbolAddress((void**)&p_hlo, g_h_lo);
        cudaGetSymbolAddress((void**)&p_wqh, g_wq_hi);
        cudaGetSymbolAddress((void**)&p_wql, g_wq_lo);
        cudaGetSymbolAddress((void**)&p_woh, g_wo_hi);
        cudaGetSymbolAddress((void**)&p_wol, g_wo_lo);
        cudaGetSymbolAddress((void**)&p_qh, g_q_hi);
        cudaGetSymbolAddress((void**)&p_ql, g_q_lo);
        cudaGetSymbolAddress((void**)&p_kh, g_k_hi);
        cudaGetSymbolAddress((void**)&p_kl, g_k_lo);
        cudaGetSymbolAddress((void**)&p_vh, g_v_hi);
        cudaGetSymbolAddress((void**)&p_vl, g_v_lo);
        cudaGetSymbolAddress((void**)&p_aoh, g_ao_hi);
        cudaGetSymbolAddress((void**)&p_aol, g_ao_lo);
        cudaGetSymbolAddress((void**)&p_m, g_m);
        cudaGetSymbolAddress((void**)&p_inv, g_inv);
        cudaFuncSetAttribute(gemm_mma_qkv, cudaFuncAttributeMaxDynamicSharedMemorySize, G_SMEM);
        cudaFuncSetAttribute(gemm_mma_out, cudaFuncAttributeMaxDynamicSharedMemorySize, G_SMEM);
        cudaFuncSetAttribute(scores_stats, cudaFuncAttributeMaxDynamicSharedMemorySize, ST_SMEM);
        cudaFuncSetAttribute(av_fused, cudaFuncAttributeMaxDynamicSharedMemorySize, FA_SMEM);
    }

    ln_kernel<<<BT, 256>>>(x, ln_g, ln_b, p_hhi, p_hlo);
    tsplit_kernel<<<dim3(QKV_N / 32, D_MODEL / 32), dim3(32, 8)>>>(qkv_w, p_wqh, p_wql, D_MODEL, QKV_N);
    tsplit_kernel<<<dim3(D_MODEL / 32, D_MODEL / 32), dim3(32, 8)>>>(out_w, p_woh, p_wol, D_MODEL, D_MODEL);

    gemm_mma_qkv<<<dim3(QKV_N / 128, BT / 256), 512, G_SMEM>>>(
        p_hhi, p_hlo, p_wqh, p_wql, qkv_b, p_qh, p_ql, p_kh, p_kl, p_vh, p_vl);

    scores_stats<<<dim3(16, 32), 256, ST_SMEM>>>(p_qh, p_ql, p_kh, p_kl, p_m, p_inv);
    av_fused<<<dim3(16, 32), 256, FA_SMEM>>>(p_qh, p_ql, p_kh, p_kl, p_vh, p_vl,
                                             p_m, p_inv, attn, p_aoh, p_aol);

    gemm_mma_out<<<dim3(D_MODEL / 128, BT / 256), 512, G_SMEM>>>(
        p_aoh, p_aol, p_woh, p_wol, out_b, x, xout);
}